// round 1
// baseline (speedup 1.0000x reference)
#include <cuda_runtime.h>

#define NB 256
#define NT 256
#define NC 384
#define NH 384
#define NBT (NB*NT)

// Scratch (device globals: no allocations allowed in kernel_launch)
__device__ float g_Q[NBT*NH];
__device__ float g_K[NBT*NH];
__device__ float g_V[NBT*NH];
__device__ float g_P[NB*NT*NT];

// ---- packed f32x2 helpers (sm_100+ packed fp32 pipe) ----
__forceinline__ __device__ unsigned long long pk2(float lo, float hi){
    unsigned long long r;
    asm("mov.b64 %0,{%1,%2};" : "=l"(r) : "f"(lo), "f"(hi));
    return r;
}
__forceinline__ __device__ void fma2(unsigned long long& d, unsigned long long a, unsigned long long b){
    asm("fma.rn.f32x2 %0,%1,%2,%0;" : "+l"(d) : "l"(a), "l"(b));
}
__forceinline__ __device__ float2 up2(unsigned long long v){
    float2 r;
    asm("mov.b64 {%0,%1},%2;" : "=f"(r.x), "=f"(r.y) : "l"(v));
    return r;
}

#define NEG_INF (__int_as_float((int)0xff800000))

// ============================================================================
// Kernel 1: QKV projections.  out[bt][h] = sum_c x[bt][c] * W[h][c]
// GEMM 65536 x 384 x 384, z selects {Q,K,V}. 128x128x16 tiles, 8x8/thread.
// ============================================================================
__global__ __launch_bounds__(256) void proj_kernel(
    const float* __restrict__ x, const float* __restrict__ Wk,
    const float* __restrict__ Wq, const float* __restrict__ Wv)
{
    __shared__ float As[16][132];   // [k][m] transposed
    __shared__ float Bs[16][132];   // [k][n] transposed

    const float* W; float* out;
    if (blockIdx.z == 0)      { W = Wq; out = g_Q; }
    else if (blockIdx.z == 1) { W = Wk; out = g_K; }
    else                      { W = Wv; out = g_V; }

    const int m0 = blockIdx.x * 128, n0 = blockIdx.y * 128;
    const int tid = threadIdx.x;
    const int r  = tid >> 2, qc  = tid & 3;
    const int cty = tid >> 4, ctx = tid & 15;

    unsigned long long acc[8][4];
    #pragma unroll
    for (int i = 0; i < 8; i++)
        #pragma unroll
        for (int j = 0; j < 4; j++) acc[i][j] = 0ULL;

    for (int k0 = 0; k0 < NC; k0 += 16) {
        #pragma unroll
        for (int p = 0; p < 2; p++) {
            int rr = r + p * 64;
            float4 va = *(const float4*)(x + (size_t)(m0 + rr) * NC + k0 + qc * 4);
            As[qc*4+0][rr] = va.x; As[qc*4+1][rr] = va.y;
            As[qc*4+2][rr] = va.z; As[qc*4+3][rr] = va.w;
            float4 vb = *(const float4*)(W + (size_t)(n0 + rr) * NC + k0 + qc * 4);
            Bs[qc*4+0][rr] = vb.x; Bs[qc*4+1][rr] = vb.y;
            Bs[qc*4+2][rr] = vb.z; Bs[qc*4+3][rr] = vb.w;
        }
        __syncthreads();
        #pragma unroll
        for (int k = 0; k < 16; k++) {
            float4 a0 = *(const float4*)&As[k][cty*8];
            float4 a1 = *(const float4*)&As[k][cty*8+4];
            float4 b0 = *(const float4*)&Bs[k][ctx*8];
            float4 b1 = *(const float4*)&Bs[k][ctx*8+4];
            unsigned long long bp[4] = { pk2(b0.x,b0.y), pk2(b0.z,b0.w),
                                         pk2(b1.x,b1.y), pk2(b1.z,b1.w) };
            float am[8] = { a0.x,a0.y,a0.z,a0.w, a1.x,a1.y,a1.z,a1.w };
            #pragma unroll
            for (int m = 0; m < 8; m++) {
                unsigned long long ap = pk2(am[m], am[m]);
                #pragma unroll
                for (int np = 0; np < 4; np++) fma2(acc[m][np], ap, bp[np]);
            }
        }
        __syncthreads();
    }

    #pragma unroll
    for (int m = 0; m < 8; m++) {
        float2 v0 = up2(acc[m][0]), v1 = up2(acc[m][1]);
        float2 v2 = up2(acc[m][2]), v3 = up2(acc[m][3]);
        size_t base = (size_t)(m0 + cty*8 + m) * NH + n0 + ctx*8;
        *(float4*)(out + base)     = make_float4(v0.x, v0.y, v1.x, v1.y);
        *(float4*)(out + base + 4) = make_float4(v2.x, v2.y, v3.x, v3.y);
    }
}

// ============================================================================
// Kernel 2a: S = Q K^T * scale, causal mask, softmax -> P (fp32 scratch).
// Per block: one batch, 64 query rows x full 256 key cols (softmax in-block).
// Warp ty owns rows ty*8..ty*8+7; lane tx holds cols {tx, 32+tx, ...}.
// Causal skip: column-pair-blocks jp > blockIdx.x never computed.
// ============================================================================
__global__ __launch_bounds__(256) void scores_kernel()
{
    __shared__ float Qs[16][68];    // [k][m]
    __shared__ float Ks[16][260];   // [k][s]

    const int b   = blockIdx.y;
    const int bx  = blockIdx.x;
    const int qt0 = bx * 64;
    const int njp = bx + 1;                 // 64-col pair-blocks needed (causal)
    const int tid = threadIdx.x;
    const int tx  = tid & 31, ty = tid >> 5;
    const int r   = tid >> 2, qc = tid & 3;
    const float* Qm = g_Q + (size_t)b * NT * NH;
    const float* Km = g_K + (size_t)b * NT * NH;

    unsigned long long acc[8][4];
    #pragma unroll
    for (int i = 0; i < 8; i++)
        #pragma unroll
        for (int j = 0; j < 4; j++) acc[i][j] = 0ULL;

    for (int k0 = 0; k0 < NH; k0 += 16) {
        {
            float4 va = *(const float4*)(Qm + (size_t)(qt0 + r) * NH + k0 + qc * 4);
            Qs[qc*4+0][r] = va.x; Qs[qc*4+1][r] = va.y;
            Qs[qc*4+2][r] = va.z; Qs[qc*4+3][r] = va.w;
        }
        #pragma unroll
        for (int p = 0; p < 4; p++) {
            int rr = r + p * 64;
            float4 vb = *(const float4*)(Km + (size_t)rr * NH + k0 + qc * 4);
            Ks[qc*4+0][rr] = vb.x; Ks[qc*4+1][rr] = vb.y;
            Ks[qc*4+2][rr] = vb.z; Ks[qc*4+3][rr] = vb.w;
        }
        __syncthreads();
        #pragma unroll
        for (int k = 0; k < 16; k++) {
            float4 a0 = *(const float4*)&Qs[k][ty*8];
            float4 a1 = *(const float4*)&Qs[k][ty*8+4];
            float am[8] = { a0.x,a0.y,a0.z,a0.w, a1.x,a1.y,a1.z,a1.w };
            unsigned long long ap[8];
            #pragma unroll
            for (int m = 0; m < 8; m++) ap[m] = pk2(am[m], am[m]);
            for (int jp = 0; jp < njp; jp++) {
                unsigned long long bp = pk2(Ks[k][jp*64 + tx], Ks[k][jp*64 + 32 + tx]);
                #pragma unroll
                for (int m = 0; m < 8; m++) fma2(acc[m][jp], ap[m], bp);
            }
        }
        __syncthreads();
    }

    const float scale = 0.05103103630798288f;  // 384^-0.5
    #pragma unroll
    for (int im = 0; im < 8; im++) {
        const int q = qt0 + ty * 8 + im;
        float e[8];
        float mx = NEG_INF;
        #pragma unroll
        for (int jp = 0; jp < 4; jp++) {
            if (jp < njp) {
                float2 w = up2(acc[im][jp]);
                int c0 = jp*64 + tx, c1 = c0 + 32;
                float w0 = (c0 <= q) ? w.x * scale : NEG_INF;
                float w1 = (c1 <= q) ? w.y * scale : NEG_INF;
                e[2*jp] = w0; e[2*jp+1] = w1;
                mx = fmaxf(mx, fmaxf(w0, w1));
            } else {
                e[2*jp] = NEG_INF; e[2*jp+1] = NEG_INF;
            }
        }
        #pragma unroll
        for (int s = 16; s > 0; s >>= 1)
            mx = fmaxf(mx, __shfl_xor_sync(0xffffffffu, mx, s));
        float sum = 0.f;
        #pragma unroll
        for (int j = 0; j < 8; j++) {
            float ex = __expf(e[j] - mx);   // exp(-inf)=0 handles masked cols
            e[j] = ex; sum += ex;
        }
        #pragma unroll
        for (int s = 16; s > 0; s >>= 1)
            sum += __shfl_xor_sync(0xffffffffu, sum, s);
        float rs = 1.0f / sum;
        float* Pr = g_P + (size_t)b * NT * NT + (size_t)q * NT;
        #pragma unroll
        for (int j = 0; j < 8; j++)
            Pr[j*32 + tx] = e[j] * rs;      // all 256 cols written (zeros past diag)
    }
}

// ============================================================================
// Kernel 2b: O = P @ V per batch. GEMM 256 x 384 x 256, 128x128x16 tiles.
// Causal skip: k tiles beyond m0+128 are all-zero P -> skipped.
// ============================================================================
__global__ __launch_bounds__(256) void pv_kernel(float* __restrict__ out)
{
    __shared__ float As[16][132];   // [k][m] transposed (P tile)
    __shared__ float Bs[16][132];   // [k][n] natural (V tile)

    const int b  = blockIdx.z;
    const int m0 = blockIdx.x * 128, n0 = blockIdx.y * 128;
    const int tid = threadIdx.x;
    const int r  = tid >> 2, qc  = tid & 3;
    const int cty = tid >> 4, ctx = tid & 15;
    const float* Pm = g_P + (size_t)b * NT * NT;
    const float* Vm = g_V + (size_t)b * NT * NH;
    const int kend = m0 + 128;      // causal: P[m][s]=0 for s>m; m0 in {0,128}

    unsigned long long acc[8][4];
    #pragma unroll
    for (int i = 0; i < 8; i++)
        #pragma unroll
        for (int j = 0; j < 4; j++) acc[i][j] = 0ULL;

    for (int k0 = 0; k0 < kend; k0 += 16) {
        #pragma unroll
        for (int p = 0; p < 2; p++) {
            int rr = r + p * 64;
            float4 va = *(const float4*)(Pm + (size_t)(m0 + rr) * NT + k0 + qc * 4);
            As[qc*4+0][rr] = va.x; As[qc*4+1][rr] = va.y;
            As[qc*4+2][rr] = va.z; As[qc*4+3][rr] = va.w;
        }
        #pragma unroll
        for (int p = 0; p < 2; p++) {
            int kr = (tid >> 5) + p * 8;   // 0..15
            int cc = (tid & 31) * 4;       // 0..124
            *(float4*)&Bs[kr][cc] =
                *(const float4*)(Vm + (size_t)(k0 + kr) * NH + n0 + cc);
        }
        __syncthreads();
        #pragma unroll
        for (int k = 0; k < 16; k++) {
            float4 a0 = *(const float4*)&As[k][cty*8];
            float4 a1 = *(const float4*)&As[k][cty*8+4];
            float4 b0 = *(const float4*)&Bs[k][ctx*8];
            float4 b1 = *(const float4*)&Bs[k][ctx*8+4];
            unsigned long long bp[4] = { pk2(b0.x,b0.y), pk2(b0.z,b0.w),
                                         pk2(b1.x,b1.y), pk2(b1.z,b1.w) };
            float am[8] = { a0.x,a0.y,a0.z,a0.w, a1.x,a1.y,a1.z,a1.w };
            #pragma unroll
            for (int m = 0; m < 8; m++) {
                unsigned long long ap = pk2(am[m], am[m]);
                #pragma unroll
                for (int np = 0; np < 4; np++) fma2(acc[m][np], ap, bp[np]);
            }
        }
        __syncthreads();
    }

    #pragma unroll
    for (int m = 0; m < 8; m++) {
        float2 v0 = up2(acc[m][0]), v1 = up2(acc[m][1]);
        float2 v2 = up2(acc[m][2]), v3 = up2(acc[m][3]);
        size_t base = (size_t)(b * NT + m0 + cty*8 + m) * NH + n0 + ctx*8;
        *(float4*)(out + base)     = make_float4(v0.x, v0.y, v1.x, v1.y);
        *(float4*)(out + base + 4) = make_float4(v2.x, v2.y, v3.x, v3.y);
    }
}

// ============================================================================
extern "C" void kernel_launch(void* const* d_in, const int* in_sizes, int n_in,
                              void* d_out, int out_size)
{
    const float* x  = (const float*)d_in[0];
    const float* Wk = (const float*)d_in[1];
    const float* Wq = (const float*)d_in[2];
    const float* Wv = (const float*)d_in[3];
    float* out = (float*)d_out;

    proj_kernel  <<<dim3(NBT/128, NH/128, 3), 256>>>(x, Wk, Wq, Wv);
    scores_kernel<<<dim3(NT/64,  NB),        256>>>();
    pv_kernel    <<<dim3(NT/128, NH/128, NB), 256>>>(out);
}

// round 2
// speedup vs baseline: 4.4920x; 4.4920x over previous
#include <cuda_runtime.h>

#define NB 256
#define NT 256
#define NC 384
#define NH 384
#define NBT (NB*NT)
#define KP 20              // padded k-stride for [row][k] smem tiles

__device__ float g_Q[(size_t)NBT*NH];
__device__ float g_K[(size_t)NBT*NH];
__device__ float g_V[(size_t)NBT*NH];
__device__ float g_P[(size_t)NB*NT*NT];

#define NEG_INF (__int_as_float((int)0xff800000))

// ---- tf32 helpers ----
__forceinline__ __device__ unsigned tf32(float f){
    unsigned r; asm("cvt.rna.tf32.f32 %0, %1;" : "=r"(r) : "f"(f)); return r;
}
// D += A(16x8) * B(8x8), tf32 in, fp32 accum
__forceinline__ __device__ void mma8(float* c, const unsigned* a, const unsigned* b){
    asm("mma.sync.aligned.m16n8k8.row.col.f32.tf32.tf32.f32 "
        "{%0,%1,%2,%3}, {%4,%5,%6,%7}, {%8,%9}, {%0,%1,%2,%3};"
        : "+f"(c[0]), "+f"(c[1]), "+f"(c[2]), "+f"(c[3])
        : "r"(a[0]), "r"(a[1]), "r"(a[2]), "r"(a[3]), "r"(b[0]), "r"(b[1]));
}

// ============================================================================
// Kernel 1: QKV projection.  out[m][h] = sum_c x[m][c] * W[h][c]
// GEMM 65536 x 384 x 384 (z selects Q/K/V). CTA tile 128x128x16,
// 8 warps in 4(m) x 2(n), warp tile 32x64 (2 m-tiles x 8 n-tiles).
// ============================================================================
__global__ __launch_bounds__(256) void proj_kernel(
    const float* __restrict__ x, const float* __restrict__ Wk,
    const float* __restrict__ Wq, const float* __restrict__ Wv)
{
    __shared__ unsigned As[128][KP];
    __shared__ unsigned Bs[128][KP];

    const float* W; float* out;
    if (blockIdx.z == 0)      { W = Wq; out = g_Q; }
    else if (blockIdx.z == 1) { W = Wk; out = g_K; }
    else                      { W = Wv; out = g_V; }

    const int m0 = blockIdx.x * 128, n0 = blockIdx.y * 128;
    const int tid  = threadIdx.x;
    const int lane = tid & 31, wid = tid >> 5;
    const int mw = wid & 3, nw = wid >> 2;
    const int g  = lane >> 2, th = lane & 3;
    const int lr = tid >> 1, lc = (tid & 1) * 8;

    float acc[2][8][4];
    #pragma unroll
    for (int i = 0; i < 2; i++)
        #pragma unroll
        for (int j = 0; j < 8; j++)
            #pragma unroll
            for (int p = 0; p < 4; p++) acc[i][j][p] = 0.f;

    for (int k0 = 0; k0 < NC; k0 += 16) {
        float4 a0 = *(const float4*)(x + (size_t)(m0+lr)*NC + k0 + lc);
        float4 a1 = *(const float4*)(x + (size_t)(m0+lr)*NC + k0 + lc + 4);
        float4 b0 = *(const float4*)(W + (size_t)(n0+lr)*NC + k0 + lc);
        float4 b1 = *(const float4*)(W + (size_t)(n0+lr)*NC + k0 + lc + 4);
        As[lr][lc+0]=tf32(a0.x); As[lr][lc+1]=tf32(a0.y);
        As[lr][lc+2]=tf32(a0.z); As[lr][lc+3]=tf32(a0.w);
        As[lr][lc+4]=tf32(a1.x); As[lr][lc+5]=tf32(a1.y);
        As[lr][lc+6]=tf32(a1.z); As[lr][lc+7]=tf32(a1.w);
        Bs[lr][lc+0]=tf32(b0.x); Bs[lr][lc+1]=tf32(b0.y);
        Bs[lr][lc+2]=tf32(b0.z); Bs[lr][lc+3]=tf32(b0.w);
        Bs[lr][lc+4]=tf32(b1.x); Bs[lr][lc+5]=tf32(b1.y);
        Bs[lr][lc+6]=tf32(b1.z); Bs[lr][lc+7]=tf32(b1.w);
        __syncthreads();

        #pragma unroll
        for (int ks = 0; ks < 16; ks += 8) {
            unsigned a[2][4];
            #pragma unroll
            for (int mt = 0; mt < 2; mt++) {
                int row = mw*32 + mt*16;
                a[mt][0] = As[row+g  ][ks+th  ];
                a[mt][1] = As[row+g+8][ks+th  ];
                a[mt][2] = As[row+g  ][ks+th+4];
                a[mt][3] = As[row+g+8][ks+th+4];
            }
            #pragma unroll
            for (int nt = 0; nt < 8; nt++) {
                unsigned bb[2];
                int col = nw*64 + nt*8 + g;
                bb[0] = Bs[col][ks+th];
                bb[1] = Bs[col][ks+th+4];
                mma8(acc[0][nt], a[0], bb);
                mma8(acc[1][nt], a[1], bb);
            }
        }
        __syncthreads();
    }

    #pragma unroll
    for (int mt = 0; mt < 2; mt++)
        #pragma unroll
        for (int nt = 0; nt < 8; nt++) {
            int row = m0 + mw*32 + mt*16 + g;
            int col = n0 + nw*64 + nt*8 + 2*th;
            *(float2*)(out + (size_t)row*NH + col)     = make_float2(acc[mt][nt][0], acc[mt][nt][1]);
            *(float2*)(out + (size_t)(row+8)*NH + col) = make_float2(acc[mt][nt][2], acc[mt][nt][3]);
        }
}

// ============================================================================
// Kernel 2: S = scale * Q K^T (causal), softmax -> P.
// One block per (64-query tile, batch). 8 warps: 4(m) x 2(n).
// Warp tile: 16 rows x 128 cols (16 n-tiles), causal tiles skipped.
// ============================================================================
__global__ __launch_bounds__(256) void scores_kernel()
{
    __shared__ unsigned Qs[64][KP];
    __shared__ unsigned Ks[256][KP];
    __shared__ float redm[2][64];
    __shared__ float reds[2][64];

    const int b = blockIdx.y, bx = blockIdx.x;
    const int qt0 = bx * 64, ncols = (bx + 1) * 64;
    const int tid  = threadIdx.x;
    const int lane = tid & 31, wid = tid >> 5;
    const int mw = wid & 3, nw = wid >> 2;
    const int g  = lane >> 2, th = lane & 3;
    const int base = nw * 128;
    int ntc = (ncols - base) / 8;
    ntc = ntc < 0 ? 0 : (ntc > 16 ? 16 : ntc);

    const float* Qm = g_Q + (size_t)b * NT * NH;
    const float* Km = g_K + (size_t)b * NT * NH;

    float acc[16][4];
    #pragma unroll
    for (int i = 0; i < 16; i++)
        #pragma unroll
        for (int p = 0; p < 4; p++) acc[i][p] = 0.f;

    const int lr = tid >> 2, lc4 = (tid & 3) * 4;
    for (int k0 = 0; k0 < NH; k0 += 16) {
        float4 q4 = *(const float4*)(Qm + (size_t)(qt0+lr)*NH + k0 + lc4);
        Qs[lr][lc4+0]=tf32(q4.x); Qs[lr][lc4+1]=tf32(q4.y);
        Qs[lr][lc4+2]=tf32(q4.z); Qs[lr][lc4+3]=tf32(q4.w);
        #pragma unroll
        for (int p = 0; p < 4; p++) {
            int rr = lr + p*64;
            float4 k4 = *(const float4*)(Km + (size_t)rr*NH + k0 + lc4);
            Ks[rr][lc4+0]=tf32(k4.x); Ks[rr][lc4+1]=tf32(k4.y);
            Ks[rr][lc4+2]=tf32(k4.z); Ks[rr][lc4+3]=tf32(k4.w);
        }
        __syncthreads();

        if (ntc > 0) {
            #pragma unroll
            for (int ks = 0; ks < 16; ks += 8) {
                unsigned a[4];
                int row = mw*16;
                a[0] = Qs[row+g  ][ks+th  ];
                a[1] = Qs[row+g+8][ks+th  ];
                a[2] = Qs[row+g  ][ks+th+4];
                a[3] = Qs[row+g+8][ks+th+4];
                #pragma unroll
                for (int nt = 0; nt < 16; nt++) {
                    if (nt < ntc) {
                        unsigned bb[2];
                        int col = base + nt*8 + g;
                        bb[0] = Ks[col][ks+th];
                        bb[1] = Ks[col][ks+th+4];
                        mma8(acc[nt], a, bb);
                    }
                }
            }
        }
        __syncthreads();
    }

    const float scale = 0.05103103630798288f;  // 384^-0.5
    const int r0 = mw*16 + g, r1 = r0 + 8;
    const int q0 = qt0 + r0, q1 = qt0 + r1;

    float mx0 = NEG_INF, mx1 = NEG_INF;
    #pragma unroll
    for (int nt = 0; nt < 16; nt++) {
        if (nt < ntc) {
            int c = base + nt*8 + 2*th;
            float s00 = (c   <= q0) ? acc[nt][0]*scale : NEG_INF;
            float s01 = (c+1 <= q0) ? acc[nt][1]*scale : NEG_INF;
            float s10 = (c   <= q1) ? acc[nt][2]*scale : NEG_INF;
            float s11 = (c+1 <= q1) ? acc[nt][3]*scale : NEG_INF;
            acc[nt][0]=s00; acc[nt][1]=s01; acc[nt][2]=s10; acc[nt][3]=s11;
            mx0 = fmaxf(mx0, fmaxf(s00, s01));
            mx1 = fmaxf(mx1, fmaxf(s10, s11));
        }
    }
    mx0 = fmaxf(mx0, __shfl_xor_sync(0xffffffffu, mx0, 1));
    mx0 = fmaxf(mx0, __shfl_xor_sync(0xffffffffu, mx0, 2));
    mx1 = fmaxf(mx1, __shfl_xor_sync(0xffffffffu, mx1, 1));
    mx1 = fmaxf(mx1, __shfl_xor_sync(0xffffffffu, mx1, 2));
    if (th == 0) { redm[nw][r0] = mx0; redm[nw][r1] = mx1; }
    __syncthreads();

    float M0 = fmaxf(redm[0][r0], redm[1][r0]);
    float M1 = fmaxf(redm[0][r1], redm[1][r1]);

    float sm0 = 0.f, sm1 = 0.f;
    #pragma unroll
    for (int nt = 0; nt < 16; nt++) {
        if (nt < ntc) {
            float e00 = __expf(acc[nt][0] - M0);
            float e01 = __expf(acc[nt][1] - M0);
            float e10 = __expf(acc[nt][2] - M1);
            float e11 = __expf(acc[nt][3] - M1);
            acc[nt][0]=e00; acc[nt][1]=e01; acc[nt][2]=e10; acc[nt][3]=e11;
            sm0 += e00 + e01; sm1 += e10 + e11;
        }
    }
    sm0 += __shfl_xor_sync(0xffffffffu, sm0, 1);
    sm0 += __shfl_xor_sync(0xffffffffu, sm0, 2);
    sm1 += __shfl_xor_sync(0xffffffffu, sm1, 1);
    sm1 += __shfl_xor_sync(0xffffffffu, sm1, 2);
    if (th == 0) { reds[nw][r0] = sm0; reds[nw][r1] = sm1; }
    __syncthreads();

    float inv0 = 1.f / (reds[0][r0] + reds[1][r0]);
    float inv1 = 1.f / (reds[0][r1] + reds[1][r1]);

    float* Pb = g_P + (size_t)b * NT * NT;
    #pragma unroll
    for (int nt = 0; nt < 16; nt++) {
        if (nt < ntc) {
            int c = base + nt*8 + 2*th;
            *(float2*)(Pb + (size_t)q0*NT + c) = make_float2(acc[nt][0]*inv0, acc[nt][1]*inv0);
            *(float2*)(Pb + (size_t)q1*NT + c) = make_float2(acc[nt][2]*inv1, acc[nt][3]*inv1);
        }
    }

    // zero-fill P columns past the causal frontier (read densely by pv_kernel)
    const int width = 256 - ncols;
    if (width > 0) {
        for (int idx = tid * 4; idx < 64 * width; idx += 256 * 4) {
            int row = idx / width, col = ncols + (idx % width);
            *(float4*)(Pb + (size_t)(qt0+row)*NT + col) = make_float4(0.f,0.f,0.f,0.f);
        }
    }
}

// ============================================================================
// Kernel 3: O = P @ V per batch.  M=256, N=384, K=kend (causal tile skip).
// CTA tile 128x128x16, 8 warps 4(m) x 2(n), warp tile 32x64.
// ============================================================================
__global__ __launch_bounds__(256) void pv_kernel(float* __restrict__ out)
{
    __shared__ unsigned Ps[128][KP];
    __shared__ unsigned Vs[16][132];

    const int b  = blockIdx.z;
    const int m0 = blockIdx.x * 128, n0 = blockIdx.y * 128;
    const int tid  = threadIdx.x;
    const int lane = tid & 31, wid = tid >> 5;
    const int mw = wid & 3, nw = wid >> 2;
    const int g  = lane >> 2, th = lane & 3;
    const int lr = tid >> 1, lc = (tid & 1) * 8;       // P tile load
    const int vkr = tid >> 4, vnc = (tid & 15) * 8;    // V tile load
    const int kend = m0 + 128;                         // causal: P zero past here

    const float* Pm = g_P + (size_t)b * NT * NT;
    const float* Vm = g_V + (size_t)b * NT * NH;

    float acc[2][8][4];
    #pragma unroll
    for (int i = 0; i < 2; i++)
        #pragma unroll
        for (int j = 0; j < 8; j++)
            #pragma unroll
            for (int p = 0; p < 4; p++) acc[i][j][p] = 0.f;

    for (int k0 = 0; k0 < kend; k0 += 16) {
        float4 p0 = *(const float4*)(Pm + (size_t)(m0+lr)*NT + k0 + lc);
        float4 p1 = *(const float4*)(Pm + (size_t)(m0+lr)*NT + k0 + lc + 4);
        Ps[lr][lc+0]=tf32(p0.x); Ps[lr][lc+1]=tf32(p0.y);
        Ps[lr][lc+2]=tf32(p0.z); Ps[lr][lc+3]=tf32(p0.w);
        Ps[lr][lc+4]=tf32(p1.x); Ps[lr][lc+5]=tf32(p1.y);
        Ps[lr][lc+6]=tf32(p1.z); Ps[lr][lc+7]=tf32(p1.w);
        float4 v0 = *(const float4*)(Vm + (size_t)(k0+vkr)*NH + n0 + vnc);
        float4 v1 = *(const float4*)(Vm + (size_t)(k0+vkr)*NH + n0 + vnc + 4);
        Vs[vkr][vnc+0]=tf32(v0.x); Vs[vkr][vnc+1]=tf32(v0.y);
        Vs[vkr][vnc+2]=tf32(v0.z); Vs[vkr][vnc+3]=tf32(v0.w);
        Vs[vkr][vnc+4]=tf32(v1.x); Vs[vkr][vnc+5]=tf32(v1.y);
        Vs[vkr][vnc+6]=tf32(v1.z); Vs[vkr][vnc+7]=tf32(v1.w);
        __syncthreads();

        #pragma unroll
        for (int ks = 0; ks < 16; ks += 8) {
            unsigned a[2][4];
            #pragma unroll
            for (int mt = 0; mt < 2; mt++) {
                int row = mw*32 + mt*16;
                a[mt][0] = Ps[row+g  ][ks+th  ];
                a[mt][1] = Ps[row+g+8][ks+th  ];
                a[mt][2] = Ps[row+g  ][ks+th+4];
                a[mt][3] = Ps[row+g+8][ks+th+4];
            }
            #pragma unroll
            for (int nt = 0; nt < 8; nt++) {
                unsigned bb[2];
                int col = nw*64 + nt*8 + g;
                bb[0] = Vs[ks+th  ][col];
                bb[1] = Vs[ks+th+4][col];
                mma8(acc[0][nt], a[0], bb);
                mma8(acc[1][nt], a[1], bb);
            }
        }
        __syncthreads();
    }

    #pragma unroll
    for (int mt = 0; mt < 2; mt++)
        #pragma unroll
        for (int nt = 0; nt < 8; nt++) {
            int row = m0 + mw*32 + mt*16 + g;
            int col = n0 + nw*64 + nt*8 + 2*th;
            size_t base_o = (size_t)(b*NT + row) * NH + col;
            *(float2*)(out + base_o)            = make_float2(acc[mt][nt][0], acc[mt][nt][1]);
            *(float2*)(out + base_o + (size_t)8*NH) = make_float2(acc[mt][nt][2], acc[mt][nt][3]);
        }
}

// ============================================================================
extern "C" void kernel_launch(void* const* d_in, const int* in_sizes, int n_in,
                              void* d_out, int out_size)
{
    const float* x  = (const float*)d_in[0];
    const float* Wk = (const float*)d_in[1];
    const float* Wq = (const float*)d_in[2];
    const float* Wv = (const float*)d_in[3];
    float* out = (float*)d_out;

    proj_kernel  <<<dim3(NBT/128, NH/128, 3), 256>>>(x, Wk, Wq, Wv);
    scores_kernel<<<dim3(NT/64,  NB),         256>>>();
    pv_kernel    <<<dim3(NT/128, NH/128, NB), 256>>>(out);
}

// round 4
// speedup vs baseline: 4.6338x; 1.0316x over previous
#include <cuda_runtime.h>
#include <cstdint>

#define NB 256
#define NT 256
#define NC 384
#define NH 384
#define NBT (NB*NT)
#define KP 20              // padded row stride (words) for 16-wide k tiles

__device__ float g_Q[(size_t)NBT*NH];
__device__ float g_K[(size_t)NBT*NH];
__device__ float g_V[(size_t)NBT*NH];
__device__ float g_P[(size_t)NB*NT*NT];

#define NEG_INF (__int_as_float((int)0xff800000))
#define PERM(k) ((((k)&3)<<2)|((k)>>2))   // k in [0,16)

__forceinline__ __device__ unsigned tf32(float f){
    unsigned r; asm("cvt.rna.tf32.f32 %0, %1;" : "=r"(r) : "f"(f)); return r;
}
__forceinline__ __device__ void mma8(float* c, const unsigned* a, const unsigned* b){
    asm("mma.sync.aligned.m16n8k8.row.col.f32.tf32.tf32.f32 "
        "{%0,%1,%2,%3}, {%4,%5,%6,%7}, {%8,%9}, {%0,%1,%2,%3};"
        : "+f"(c[0]), "+f"(c[1]), "+f"(c[2]), "+f"(c[3])
        : "r"(a[0]), "r"(a[1]), "r"(a[2]), "r"(a[3]), "r"(b[0]), "r"(b[1]));
}

// ============================================================================
// Kernel 1: QKV projection. out[m][h] = sum_c x[m][c] * W[h][c]
// CTA tile 128x128x16, warps 4(m) x 2(n), warp tile 32x64.
// Permuted smem layout -> LDS.128 fragment loads; register prefetch.
// ============================================================================
__global__ __launch_bounds__(256) void proj_kernel(
    const float* __restrict__ x, const float* __restrict__ Wk,
    const float* __restrict__ Wq, const float* __restrict__ Wv)
{
    __shared__ unsigned As[128][KP];
    __shared__ unsigned Bs[128][KP];

    const float* W; float* out;
    if (blockIdx.z == 0)      { W = Wq; out = g_Q; }
    else if (blockIdx.z == 1) { W = Wk; out = g_K; }
    else                      { W = Wv; out = g_V; }

    const int m0 = blockIdx.x * 128, n0 = blockIdx.y * 128;
    const int tid  = threadIdx.x;
    const int lane = tid & 31, wid = tid >> 5;
    const int mw = wid & 3, nw = wid >> 2;
    const int g  = lane >> 2, th = lane & 3;
    const int lr = tid >> 1, lc = (tid & 1) * 8;   // fill: row, k-offset {0,8}

    float acc[2][8][4];
    #pragma unroll
    for (int i = 0; i < 2; i++)
        #pragma unroll
        for (int j = 0; j < 8; j++)
            #pragma unroll
            for (int p = 0; p < 4; p++) acc[i][j][p] = 0.f;

    const float* pA = x + (size_t)(m0+lr)*NC + lc;
    const float* pB = W + (size_t)(n0+lr)*NC + lc;
    float4 fa0 = *(const float4*)(pA);
    float4 fa1 = *(const float4*)(pA + 4);
    float4 fb0 = *(const float4*)(pB);
    float4 fb1 = *(const float4*)(pB + 4);

    for (int it = 0; it < NC/16; it++) {
        {   // store prefetched tile (cvt + permuted scatter)
            float va[8] = {fa0.x,fa0.y,fa0.z,fa0.w, fa1.x,fa1.y,fa1.z,fa1.w};
            float vb[8] = {fb0.x,fb0.y,fb0.z,fb0.w, fb1.x,fb1.y,fb1.z,fb1.w};
            #pragma unroll
            for (int j = 0; j < 8; j++) {
                As[lr][PERM(lc + j)] = tf32(va[j]);
                Bs[lr][PERM(lc + j)] = tf32(vb[j]);
            }
        }
        __syncthreads();
        if (it + 1 < NC/16) {
            const float* qA = pA + (it+1)*16;
            const float* qB = pB + (it+1)*16;
            fa0 = *(const float4*)(qA);
            fa1 = *(const float4*)(qA + 4);
            fb0 = *(const float4*)(qB);
            fb1 = *(const float4*)(qB + 4);
        }

        unsigned a[2][2][4];
        #pragma unroll
        for (int mt = 0; mt < 2; mt++) {
            int row = mw*32 + mt*16;
            uint4 v0 = *(const uint4*)&As[row+g  ][th*4];
            uint4 v1 = *(const uint4*)&As[row+g+8][th*4];
            a[mt][0][0]=v0.x; a[mt][0][1]=v1.x; a[mt][0][2]=v0.y; a[mt][0][3]=v1.y;
            a[mt][1][0]=v0.z; a[mt][1][1]=v1.z; a[mt][1][2]=v0.w; a[mt][1][3]=v1.w;
        }
        #pragma unroll
        for (int nt = 0; nt < 8; nt++) {
            uint4 w = *(const uint4*)&Bs[nw*64 + nt*8 + g][th*4];
            unsigned b0[2] = {w.x, w.y}, b1[2] = {w.z, w.w};
            mma8(acc[0][nt], a[0][0], b0);
            mma8(acc[1][nt], a[1][0], b0);
            mma8(acc[0][nt], a[0][1], b1);
            mma8(acc[1][nt], a[1][1], b1);
        }
        __syncthreads();
    }

    #pragma unroll
    for (int mt = 0; mt < 2; mt++)
        #pragma unroll
        for (int nt = 0; nt < 8; nt++) {
            int row = m0 + mw*32 + mt*16 + g;
            int col = n0 + nw*64 + nt*8 + 2*th;
            *(float2*)(out + (size_t)row*NH + col)     = make_float2(acc[mt][nt][0], acc[mt][nt][1]);
            *(float2*)(out + (size_t)(row+8)*NH + col) = make_float2(acc[mt][nt][2], acc[mt][nt][3]);
        }
}

// ============================================================================
// Kernel 2: S = scale * Q K^T (causal), softmax -> P.
// Block = (64-query tile, batch). Warps 4(m) x 2(n); warp tile 16x128.
// ============================================================================
__global__ __launch_bounds__(256) void scores_kernel()
{
    __shared__ unsigned Qs[64][KP];
    __shared__ unsigned Ks[256][KP];
    __shared__ float redm[2][64];
    __shared__ float reds[2][64];

    const int b = blockIdx.y, bx = blockIdx.x;
    const int qt0 = bx * 64, ncols = (bx + 1) * 64;
    const int tid  = threadIdx.x;
    const int lane = tid & 31, wid = tid >> 5;
    const int mw = wid & 3, nw = wid >> 2;
    const int g  = lane >> 2, th = lane & 3;
    const int base = nw * 128;
    int ntc = (ncols - base) / 8;
    ntc = ntc < 0 ? 0 : (ntc > 16 ? 16 : ntc);

    const float* Qm = g_Q + (size_t)b * NT * NH;
    const float* Km = g_K + (size_t)b * NT * NH;

    float acc[16][4];
    #pragma unroll
    for (int i = 0; i < 16; i++)
        #pragma unroll
        for (int p = 0; p < 4; p++) acc[i][p] = 0.f;

    const int lr = tid >> 2, cf = tid & 3, lc4 = cf * 4;
    const float* pQ = Qm + (size_t)(qt0+lr)*NH + lc4;
    const float* pK = Km + (size_t)lr*NH + lc4;
    float4 fq = *(const float4*)(pQ);
    float4 fk[4];
    #pragma unroll
    for (int p = 0; p < 4; p++) fk[p] = *(const float4*)(pK + (size_t)p*64*NH);

    for (int it = 0; it < NH/16; it++) {
        {
            float vq[4] = {fq.x, fq.y, fq.z, fq.w};
            #pragma unroll
            for (int j = 0; j < 4; j++) Qs[lr][j*4 + cf] = tf32(vq[j]);
            #pragma unroll
            for (int p = 0; p < 4; p++) {
                float vk[4] = {fk[p].x, fk[p].y, fk[p].z, fk[p].w};
                #pragma unroll
                for (int j = 0; j < 4; j++) Ks[lr + p*64][j*4 + cf] = tf32(vk[j]);
            }
        }
        __syncthreads();
        if (it + 1 < NH/16) {
            fq = *(const float4*)(pQ + (it+1)*16);
            #pragma unroll
            for (int p = 0; p < 4; p++)
                fk[p] = *(const float4*)(pK + (size_t)p*64*NH + (it+1)*16);
        }

        if (ntc > 0) {
            unsigned a[2][4];
            {
                int row = mw*16;
                uint4 v0 = *(const uint4*)&Qs[row+g  ][th*4];
                uint4 v1 = *(const uint4*)&Qs[row+g+8][th*4];
                a[0][0]=v0.x; a[0][1]=v1.x; a[0][2]=v0.y; a[0][3]=v1.y;
                a[1][0]=v0.z; a[1][1]=v1.z; a[1][2]=v0.w; a[1][3]=v1.w;
            }
            #pragma unroll
            for (int nt = 0; nt < 16; nt++) {
                if (nt < ntc) {
                    uint4 w = *(const uint4*)&Ks[base + nt*8 + g][th*4];
                    unsigned b0[2] = {w.x, w.y}, b1[2] = {w.z, w.w};
                    mma8(acc[nt], a[0], b0);
                    mma8(acc[nt], a[1], b1);
                }
            }
        }
        __syncthreads();
    }

    const float scale = 0.05103103630798288f;  // 384^-0.5
    const int r0 = mw*16 + g, r1 = r0 + 8;
    const int q0 = qt0 + r0, q1 = qt0 + r1;

    float mx0 = NEG_INF, mx1 = NEG_INF;
    #pragma unroll
    for (int nt = 0; nt < 16; nt++) {
        if (nt < ntc) {
            int c = base + nt*8 + 2*th;
            float s00 = (c   <= q0) ? acc[nt][0]*scale : NEG_INF;
            float s01 = (c+1 <= q0) ? acc[nt][1]*scale : NEG_INF;
            float s10 = (c   <= q1) ? acc[nt][2]*scale : NEG_INF;
            float s11 = (c+1 <= q1) ? acc[nt][3]*scale : NEG_INF;
            acc[nt][0]=s00; acc[nt][1]=s01; acc[nt][2]=s10; acc[nt][3]=s11;
            mx0 = fmaxf(mx0, fmaxf(s00, s01));
            mx1 = fmaxf(mx1, fmaxf(s10, s11));
        }
    }
    mx0 = fmaxf(mx0, __shfl_xor_sync(0xffffffffu, mx0, 1));
    mx0 = fmaxf(mx0, __shfl_xor_sync(0xffffffffu, mx0, 2));
    mx1 = fmaxf(mx1, __shfl_xor_sync(0xffffffffu, mx1, 1));
    mx1 = fmaxf(mx1, __shfl_xor_sync(0xffffffffu, mx1, 2));
    if (th == 0) { redm[nw][r0] = mx0; redm[nw][r1] = mx1; }
    __syncthreads();

    float M0 = fmaxf(redm[0][r0], redm[1][r0]);
    float M1 = fmaxf(redm[0][r1], redm[1][r1]);

    float sm0 = 0.f, sm1 = 0.f;
    #pragma unroll
    for (int nt = 0; nt < 16; nt++) {
        if (nt < ntc) {
            float e00 = __expf(acc[nt][0] - M0);
            float e01 = __expf(acc[nt][1] - M0);
            float e10 = __expf(acc[nt][2] - M1);
            float e11 = __expf(acc[nt][3] - M1);
            acc[nt][0]=e00; acc[nt][1]=e01; acc[nt][2]=e10; acc[nt][3]=e11;
            sm0 += e00 + e01; sm1 += e10 + e11;
        }
    }
    sm0 += __shfl_xor_sync(0xffffffffu, sm0, 1);
    sm0 += __shfl_xor_sync(0xffffffffu, sm0, 2);
    sm1 += __shfl_xor_sync(0xffffffffu, sm1, 1);
    sm1 += __shfl_xor_sync(0xffffffffu, sm1, 2);
    if (th == 0) { reds[nw][r0] = sm0; reds[nw][r1] = sm1; }
    __syncthreads();

    float inv0 = 1.f / (reds[0][r0] + reds[1][r0]);
    float inv1 = 1.f / (reds[0][r1] + reds[1][r1]);

    float* Pb = g_P + (size_t)b * NT * NT;
    #pragma unroll
    for (int nt = 0; nt < 16; nt++) {
        if (nt < ntc) {
            int c = base + nt*8 + 2*th;
            *(float2*)(Pb + (size_t)q0*NT + c) = make_float2(acc[nt][0]*inv0, acc[nt][1]*inv0);
            *(float2*)(Pb + (size_t)q1*NT + c) = make_float2(acc[nt][2]*inv1, acc[nt][3]*inv1);
        }
    }

    const int width = 256 - ncols;
    if (width > 0) {
        for (int idx = tid * 4; idx < 64 * width; idx += 256 * 4) {
            int row = idx / width, col = ncols + (idx % width);
            *(float4*)(Pb + (size_t)(qt0+row)*NT + col) = make_float4(0.f,0.f,0.f,0.f);
        }
    }
}

// ============================================================================
// Kernel 3: O = P @ V per batch. CTA 128x128x16, causal k-skip.
// P side permuted (LDS.128), V side natural scalar layout.
// ============================================================================
__global__ __launch_bounds__(256) void pv_kernel(float* __restrict__ out)
{
    __shared__ unsigned Ps[128][KP];
    __shared__ unsigned Vs[16][132];

    const int b  = blockIdx.z;
    const int m0 = blockIdx.x * 128, n0 = blockIdx.y * 128;
    const int tid  = threadIdx.x;
    const int lane = tid & 31, wid = tid >> 5;
    const int mw = wid & 3, nw = wid >> 2;
    const int g  = lane >> 2, th = lane & 3;
    const int lr = tid >> 1, lc = (tid & 1) * 8;
    const int vkr = tid >> 4, vnc = (tid & 15) * 8;
    const int kend = m0 + 128;
    const int nit = kend / 16;

    const float* Pm = g_P + (size_t)b * NT * NT;
    const float* Vm = g_V + (size_t)b * NT * NH;

    float acc[2][8][4];
    #pragma unroll
    for (int i = 0; i < 2; i++)
        #pragma unroll
        for (int j = 0; j < 8; j++)
            #pragma unroll
            for (int p = 0; p < 4; p++) acc[i][j][p] = 0.f;

    const float* pP = Pm + (size_t)(m0+lr)*NT + lc;
    const float* pV = Vm + (size_t)vkr*NH + n0 + vnc;
    float4 fp0 = *(const float4*)(pP);
    float4 fp1 = *(const float4*)(pP + 4);
    float4 fv0 = *(const float4*)(pV);
    float4 fv1 = *(const float4*)(pV + 4);

    for (int it = 0; it < nit; it++) {
        {
            float vp[8] = {fp0.x,fp0.y,fp0.z,fp0.w, fp1.x,fp1.y,fp1.z,fp1.w};
            #pragma unroll
            for (int j = 0; j < 8; j++) Ps[lr][PERM(lc + j)] = tf32(vp[j]);
            Vs[vkr][vnc+0]=tf32(fv0.x); Vs[vkr][vnc+1]=tf32(fv0.y);
            Vs[vkr][vnc+2]=tf32(fv0.z); Vs[vkr][vnc+3]=tf32(fv0.w);
            Vs[vkr][vnc+4]=tf32(fv1.x); Vs[vkr][vnc+5]=tf32(fv1.y);
            Vs[vkr][vnc+6]=tf32(fv1.z); Vs[vkr][vnc+7]=tf32(fv1.w);
        }
        __syncthreads();
        if (it + 1 < nit) {
            fp0 = *(const float4*)(pP + (it+1)*16);
            fp1 = *(const float4*)(pP + (it+1)*16 + 4);
            fv0 = *(const float4*)(pV + (size_t)(it+1)*16*NH);
            fv1 = *(const float4*)(pV + (size_t)(it+1)*16*NH + 4);
        }

        unsigned a[2][2][4];
        #pragma unroll
        for (int mt = 0; mt < 2; mt++) {
            int row = mw*32 + mt*16;
            uint4 v0 = *(const uint4*)&Ps[row+g  ][th*4];
            uint4 v1 = *(const uint4*)&Ps[row+g+8][th*4];
            a[mt][0][0]=v0.x; a[mt][0][1]=v1.x; a[mt][0][2]=v0.y; a[mt][0][3]=v1.y;
            a[mt][1][0]=v0.z; a[mt][1][1]=v1.z; a[mt][1][2]=v0.w; a[mt][1][3]=v1.w;
        }
        #pragma unroll
        for (int nt = 0; nt < 8; nt++) {
            int col = nw*64 + nt*8 + g;
            unsigned b0[2] = { Vs[th  ][col], Vs[th+4 ][col] };
            unsigned b1[2] = { Vs[th+8][col], Vs[th+12][col] };
            mma8(acc[0][nt], a[0][0], b0);
            mma8(acc[1][nt], a[1][0], b0);
            mma8(acc[0][nt], a[0][1], b1);
            mma8(acc[1][nt], a[1][1], b1);
        }
        __syncthreads();
    }

    #pragma unroll
    for (int mt = 0; mt < 2; mt++)
        #pragma unroll
        for (int nt = 0; nt < 8; nt++) {
            int row = m0 + mw*32 + mt*16 + g;
            int col = n0 + nw*64 + nt*8 + 2*th;
            size_t base_o = (size_t)(b*NT + row) * NH + col;
            *(float2*)(out + base_o)                = make_float2(acc[mt][nt][0], acc[mt][nt][1]);
            *(float2*)(out + base_o + (size_t)8*NH) = make_float2(acc[mt][nt][2], acc[mt][nt][3]);
        }
}

// ============================================================================
extern "C" void kernel_launch(void* const* d_in, const int* in_sizes, int n_in,
                              void* d_out, int out_size)
{
    const float* x  = (const float*)d_in[0];
    const float* Wk = (const float*)d_in[1];
    const float* Wq = (const float*)d_in[2];
    const float* Wv = (const float*)d_in[3];
    float* out = (float*)d_out;

    proj_kernel  <<<dim3(NBT/128, NH/128, 3), 256>>>(x, Wk, Wq, Wv);
    scores_kernel<<<dim3(NT/64,  NB),         256>>>();
    pv_kernel    <<<dim3(NT/128, NH/128, NB), 256>>>(out);
}

// round 5
// speedup vs baseline: 6.7897x; 1.4653x over previous
#include <cuda_runtime.h>
#include <cuda_fp16.h>
#include <cstdint>

#define NB 256
#define NT 256
#define NC 384
#define NH 384
#define NBT (NB*NT)

__device__ __half g_Q[(size_t)NBT*NH];
__device__ __half g_K[(size_t)NBT*NH];
__device__ __half g_V[(size_t)NBT*NH];
__device__ __half g_P[(size_t)NB*NT*NT];

#define NEG_INF (__int_as_float((int)0xff800000))

__forceinline__ __device__ unsigned h2(float a, float b){
    __half2 h = __floats2half2_rn(a, b);
    return *reinterpret_cast<unsigned*>(&h);
}
// D += A(16x16) * B(16x8), fp16 in, fp32 accum
__forceinline__ __device__ void mma16(float* c, const unsigned* a, const unsigned* b){
    asm("mma.sync.aligned.m16n8k16.row.col.f32.f16.f16.f32 "
        "{%0,%1,%2,%3}, {%4,%5,%6,%7}, {%8,%9}, {%0,%1,%2,%3};"
        : "+f"(c[0]), "+f"(c[1]), "+f"(c[2]), "+f"(c[3])
        : "r"(a[0]), "r"(a[1]), "r"(a[2]), "r"(a[3]), "r"(b[0]), "r"(b[1]));
}

// ============================================================================
// Kernel 1: QKV projection. out[m][h] = sum_c x[m][c] * W[h][c] (fp16 out)
// CTA 128x128, k-tile 16. Warps 4(m) x 2(n), warp tile 32x64.
// smem rows = 8 half2 words (stride 8: LDS banks 8g+th, conflict-free).
// ============================================================================
__global__ __launch_bounds__(256) void proj_kernel(
    const float* __restrict__ x, const float* __restrict__ Wk,
    const float* __restrict__ Wq, const float* __restrict__ Wv)
{
    __shared__ __align__(16) unsigned As[128][8];
    __shared__ __align__(16) unsigned Bs[128][8];

    const float* W; __half* out;
    if (blockIdx.z == 0)      { W = Wq; out = g_Q; }
    else if (blockIdx.z == 1) { W = Wk; out = g_K; }
    else                      { W = Wv; out = g_V; }

    const int m0 = blockIdx.x * 128, n0 = blockIdx.y * 128;
    const int tid  = threadIdx.x;
    const int lane = tid & 31, wid = tid >> 5;
    const int mw = wid & 3, nw = wid >> 2;
    const int g  = lane >> 2, th = lane & 3;
    const int lr = tid >> 1, j = tid & 1, lc = j * 8;

    float acc[2][8][4];
    #pragma unroll
    for (int i = 0; i < 2; i++)
        #pragma unroll
        for (int q = 0; q < 8; q++)
            #pragma unroll
            for (int p = 0; p < 4; p++) acc[i][q][p] = 0.f;

    const float* pA = x + (size_t)(m0+lr)*NC + lc;
    const float* pB = W + (size_t)(n0+lr)*NC + lc;
    float4 fa0 = *(const float4*)(pA);
    float4 fa1 = *(const float4*)(pA + 4);
    float4 fb0 = *(const float4*)(pB);
    float4 fb1 = *(const float4*)(pB + 4);

    for (int it = 0; it < NC/16; it++) {
        *(uint4*)&As[lr][4*j] = make_uint4(h2(fa0.x,fa0.y), h2(fa0.z,fa0.w),
                                           h2(fa1.x,fa1.y), h2(fa1.z,fa1.w));
        *(uint4*)&Bs[lr][4*j] = make_uint4(h2(fb0.x,fb0.y), h2(fb0.z,fb0.w),
                                           h2(fb1.x,fb1.y), h2(fb1.z,fb1.w));
        __syncthreads();
        if (it + 1 < NC/16) {
            const float* qA = pA + (it+1)*16;
            const float* qB = pB + (it+1)*16;
            fa0 = *(const float4*)(qA);  fa1 = *(const float4*)(qA + 4);
            fb0 = *(const float4*)(qB);  fb1 = *(const float4*)(qB + 4);
        }

        unsigned a[2][4];
        #pragma unroll
        for (int mt = 0; mt < 2; mt++) {
            int row = mw*32 + mt*16;
            a[mt][0] = As[row+g  ][th  ];
            a[mt][1] = As[row+g+8][th  ];
            a[mt][2] = As[row+g  ][th+4];
            a[mt][3] = As[row+g+8][th+4];
        }
        #pragma unroll
        for (int nt = 0; nt < 8; nt++) {
            int col = nw*64 + nt*8 + g;
            unsigned b[2] = { Bs[col][th], Bs[col][th+4] };
            mma16(acc[0][nt], a[0], b);
            mma16(acc[1][nt], a[1], b);
        }
        __syncthreads();
    }

    #pragma unroll
    for (int mt = 0; mt < 2; mt++)
        #pragma unroll
        for (int nt = 0; nt < 8; nt++) {
            int row = m0 + mw*32 + mt*16 + g;
            int col = n0 + nw*64 + nt*8 + 2*th;
            *(unsigned*)(out + (size_t)row*NH + col)     = h2(acc[mt][nt][0], acc[mt][nt][1]);
            *(unsigned*)(out + (size_t)(row+8)*NH + col) = h2(acc[mt][nt][2], acc[mt][nt][3]);
        }
}

// ============================================================================
// Kernel 2: S = scale * Q K^T (causal), softmax -> P (fp16).
// Block = (64-query tile, batch). Warps 4(m) x 2(n); warp tile 16x128.
// ============================================================================
__global__ __launch_bounds__(256) void scores_kernel()
{
    __shared__ __align__(16) unsigned Qs[64][8];
    __shared__ __align__(16) unsigned Ks[256][8];
    __shared__ float redm[2][64];
    __shared__ float reds[2][64];

    const int b = blockIdx.y, bx = blockIdx.x;
    const int qt0 = bx * 64, ncols = (bx + 1) * 64;
    const int tid  = threadIdx.x;
    const int lane = tid & 31, wid = tid >> 5;
    const int mw = wid & 3, nw = wid >> 2;
    const int g  = lane >> 2, th = lane & 3;
    const int base = nw * 128;
    int ntc = (ncols - base) / 8;
    ntc = ntc < 0 ? 0 : (ntc > 16 ? 16 : ntc);

    const __half* Qm = g_Q + (size_t)b * NT * NH;
    const __half* Km = g_K + (size_t)b * NT * NH;

    float acc[16][4];
    #pragma unroll
    for (int i = 0; i < 16; i++)
        #pragma unroll
        for (int p = 0; p < 4; p++) acc[i][p] = 0.f;

    const int lr = tid >> 1, j = tid & 1;
    const __half* pQ = Qm + (size_t)(qt0+lr)*NH + j*8;
    const __half* pK = Km + (size_t)lr*NH + j*8;
    uint4 fq;
    if (tid < 128) fq = *(const uint4*)(pQ);
    uint4 fk0 = *(const uint4*)(pK);
    uint4 fk1 = *(const uint4*)(pK + (size_t)128*NH);

    for (int it = 0; it < NH/16; it++) {
        if (tid < 128) *(uint4*)&Qs[lr][4*j] = fq;
        *(uint4*)&Ks[lr    ][4*j] = fk0;
        *(uint4*)&Ks[lr+128][4*j] = fk1;
        __syncthreads();
        if (it + 1 < NH/16) {
            if (tid < 128) fq = *(const uint4*)(pQ + (it+1)*16);
            fk0 = *(const uint4*)(pK + (it+1)*16);
            fk1 = *(const uint4*)(pK + (size_t)128*NH + (it+1)*16);
        }

        if (ntc > 0) {
            unsigned a[4];
            int row = mw*16;
            a[0] = Qs[row+g  ][th  ];
            a[1] = Qs[row+g+8][th  ];
            a[2] = Qs[row+g  ][th+4];
            a[3] = Qs[row+g+8][th+4];
            #pragma unroll
            for (int nt = 0; nt < 16; nt++) {
                if (nt < ntc) {
                    int col = base + nt*8 + g;
                    unsigned bb[2] = { Ks[col][th], Ks[col][th+4] };
                    mma16(acc[nt], a, bb);
                }
            }
        }
        __syncthreads();
    }

    const float scale = 0.05103103630798288f;  // 384^-0.5
    const int r0 = mw*16 + g, r1 = r0 + 8;
    const int q0 = qt0 + r0, q1 = qt0 + r1;

    float mx0 = NEG_INF, mx1 = NEG_INF;
    #pragma unroll
    for (int nt = 0; nt < 16; nt++) {
        if (nt < ntc) {
            int c = base + nt*8 + 2*th;
            float s00 = (c   <= q0) ? acc[nt][0]*scale : NEG_INF;
            float s01 = (c+1 <= q0) ? acc[nt][1]*scale : NEG_INF;
            float s10 = (c   <= q1) ? acc[nt][2]*scale : NEG_INF;
            float s11 = (c+1 <= q1) ? acc[nt][3]*scale : NEG_INF;
            acc[nt][0]=s00; acc[nt][1]=s01; acc[nt][2]=s10; acc[nt][3]=s11;
            mx0 = fmaxf(mx0, fmaxf(s00, s01));
            mx1 = fmaxf(mx1, fmaxf(s10, s11));
        }
    }
    mx0 = fmaxf(mx0, __shfl_xor_sync(0xffffffffu, mx0, 1));
    mx0 = fmaxf(mx0, __shfl_xor_sync(0xffffffffu, mx0, 2));
    mx1 = fmaxf(mx1, __shfl_xor_sync(0xffffffffu, mx1, 1));
    mx1 = fmaxf(mx1, __shfl_xor_sync(0xffffffffu, mx1, 2));
    if (th == 0) { redm[nw][r0] = mx0; redm[nw][r1] = mx1; }
    __syncthreads();

    float M0 = fmaxf(redm[0][r0], redm[1][r0]);
    float M1 = fmaxf(redm[0][r1], redm[1][r1]);

    float sm0 = 0.f, sm1 = 0.f;
    #pragma unroll
    for (int nt = 0; nt < 16; nt++) {
        if (nt < ntc) {
            float e00 = __expf(acc[nt][0] - M0);
            float e01 = __expf(acc[nt][1] - M0);
            float e10 = __expf(acc[nt][2] - M1);
            float e11 = __expf(acc[nt][3] - M1);
            acc[nt][0]=e00; acc[nt][1]=e01; acc[nt][2]=e10; acc[nt][3]=e11;
            sm0 += e00 + e01; sm1 += e10 + e11;
        }
    }
    sm0 += __shfl_xor_sync(0xffffffffu, sm0, 1);
    sm0 += __shfl_xor_sync(0xffffffffu, sm0, 2);
    sm1 += __shfl_xor_sync(0xffffffffu, sm1, 1);
    sm1 += __shfl_xor_sync(0xffffffffu, sm1, 2);
    if (th == 0) { reds[nw][r0] = sm0; reds[nw][r1] = sm1; }
    __syncthreads();

    float inv0 = 1.f / (reds[0][r0] + reds[1][r0]);
    float inv1 = 1.f / (reds[0][r1] + reds[1][r1]);

    __half* Pb = g_P + (size_t)b * NT * NT;
    #pragma unroll
    for (int nt = 0; nt < 16; nt++) {
        if (nt < ntc) {
            int c = base + nt*8 + 2*th;
            *(unsigned*)(Pb + (size_t)q0*NT + c) = h2(acc[nt][0]*inv0, acc[nt][1]*inv0);
            *(unsigned*)(Pb + (size_t)q1*NT + c) = h2(acc[nt][2]*inv1, acc[nt][3]*inv1);
        }
    }

    // zero-fill past causal frontier (pv reads dense tiles)
    const int width = 256 - ncols;
    if (width > 0) {
        const int w8 = width >> 3;
        const uint4 z = make_uint4(0,0,0,0);
        for (int i = tid; i < 64 * w8; i += 256) {
            int row = i / w8, cc = ncols + (i - row*w8)*8;
            *(uint4*)(Pb + (size_t)(qt0+row)*NT + cc) = z;
        }
    }
}

// ============================================================================
// Kernel 3: O = P @ V per batch (fp32 out). CTA 128x128x16, causal k-skip.
// P natural fp16 pairs; V pair-packed transposed smem (Vs2[pair][n]).
// ============================================================================
__global__ __launch_bounds__(256) void pv_kernel(float* __restrict__ out)
{
    __shared__ __align__(16) unsigned Ps[128][8];
    __shared__ __align__(16) unsigned Vs2[8][136];

    const int b  = blockIdx.z;
    const int m0 = blockIdx.x * 128, n0 = blockIdx.y * 128;
    const int tid  = threadIdx.x;
    const int lane = tid & 31, wid = tid >> 5;
    const int mw = wid & 3, nw = wid >> 2;
    const int g  = lane >> 2, th = lane & 3;
    const int lr = tid >> 1, j = tid & 1;
    const int vp = tid >> 5, vl = tid & 31;          // V fill: pair, n-chunk
    const int nit = (m0 + 128) / 16;

    const __half* Pm = g_P + (size_t)b * NT * NT;
    const __half* Vm = g_V + (size_t)b * NT * NH;

    float acc[2][8][4];
    #pragma unroll
    for (int i = 0; i < 2; i++)
        #pragma unroll
        for (int q = 0; q < 8; q++)
            #pragma unroll
            for (int p = 0; p < 4; p++) acc[i][q][p] = 0.f;

    const __half* pP = Pm + (size_t)(m0+lr)*NT + j*8;
    const __half* pV = Vm + (size_t)(2*vp)*NH + n0 + 4*vl;
    uint4 fp = *(const uint4*)(pP);
    uint2 fv0 = *(const uint2*)(pV);
    uint2 fv1 = *(const uint2*)(pV + NH);

    for (int it = 0; it < nit; it++) {
        *(uint4*)&Ps[lr][4*j] = fp;
        *(uint4*)&Vs2[vp][4*vl] = make_uint4(
            __byte_perm(fv0.x, fv1.x, 0x5410), __byte_perm(fv0.x, fv1.x, 0x7632),
            __byte_perm(fv0.y, fv1.y, 0x5410), __byte_perm(fv0.y, fv1.y, 0x7632));
        __syncthreads();
        if (it + 1 < nit) {
            fp  = *(const uint4*)(pP + (it+1)*16);
            fv0 = *(const uint2*)(pV + (size_t)(it+1)*16*NH);
            fv1 = *(const uint2*)(pV + (size_t)(it+1)*16*NH + NH);
        }

        unsigned a[2][4];
        #pragma unroll
        for (int mt = 0; mt < 2; mt++) {
            int row = mw*32 + mt*16;
            a[mt][0] = Ps[row+g  ][th  ];
            a[mt][1] = Ps[row+g+8][th  ];
            a[mt][2] = Ps[row+g  ][th+4];
            a[mt][3] = Ps[row+g+8][th+4];
        }
        #pragma unroll
        for (int nt = 0; nt < 8; nt++) {
            int col = nw*64 + nt*8 + g;
            unsigned bb[2] = { Vs2[th][col], Vs2[th+4][col] };
            mma16(acc[0][nt], a[0], bb);
            mma16(acc[1][nt], a[1], bb);
        }
        __syncthreads();
    }

    #pragma unroll
    for (int mt = 0; mt < 2; mt++)
        #pragma unroll
        for (int nt = 0; nt < 8; nt++) {
            int row = m0 + mw*32 + mt*16 + g;
            int col = n0 + nw*64 + nt*8 + 2*th;
            size_t base_o = (size_t)(b*NT + row) * NH + col;
            *(float2*)(out + base_o)                = make_float2(acc[mt][nt][0], acc[mt][nt][1]);
            *(float2*)(out + base_o + (size_t)8*NH) = make_float2(acc[mt][nt][2], acc[mt][nt][3]);
        }
}

// ============================================================================
extern "C" void kernel_launch(void* const* d_in, const int* in_sizes, int n_in,
                              void* d_out, int out_size)
{
    const float* x  = (const float*)d_in[0];
    const float* Wk = (const float*)d_in[1];
    const float* Wq = (const float*)d_in[2];
    const float* Wv = (const float*)d_in[3];
    float* out = (float*)d_out;

    proj_kernel  <<<dim3(NBT/128, NH/128, 3), 256>>>(x, Wk, Wq, Wv);
    scores_kernel<<<dim3(NT/64,  NB),         256>>>();
    pv_kernel    <<<dim3(NT/128, NH/128, NB), 256>>>(out);
}

// round 6
// speedup vs baseline: 9.8306x; 1.4479x over previous
#include <cuda_runtime.h>
#include <cuda_fp16.h>
#include <cstdint>

#define NB 256
#define NT 256
#define NC 384
#define NH 384
#define NBT (NB*NT)

__device__ __half g_X16[(size_t)NBT*NC];
__device__ __half g_Wh[3][(size_t)NH*NC];
__device__ __half g_Q[(size_t)NBT*NH];
__device__ __half g_K[(size_t)NBT*NH];
__device__ __half g_V[(size_t)NBT*NH];
__device__ __half g_P[(size_t)NB*NT*NT];

#define NEG_INF (__int_as_float((int)0xff800000))

__forceinline__ __device__ unsigned h2(float a, float b){
    __half2 h = __floats2half2_rn(a, b);
    return *reinterpret_cast<unsigned*>(&h);
}
__forceinline__ __device__ void mma16(float* c, const unsigned* a, const unsigned* b){
    asm("mma.sync.aligned.m16n8k16.row.col.f32.f16.f16.f32 "
        "{%0,%1,%2,%3}, {%4,%5,%6,%7}, {%8,%9}, {%0,%1,%2,%3};"
        : "+f"(c[0]), "+f"(c[1]), "+f"(c[2]), "+f"(c[3])
        : "r"(a[0]), "r"(a[1]), "r"(a[2]), "r"(a[3]), "r"(b[0]), "r"(b[1]));
}
__forceinline__ __device__ unsigned su32(const void* p){
    return (unsigned)__cvta_generic_to_shared(p);
}
#define CPA(dst,src) asm volatile("cp.async.ca.shared.global [%0], [%1], 16;" :: "r"(dst), "l"(src) : "memory")
#define CPC()        asm volatile("cp.async.commit_group;" ::: "memory")
#define CPW(n)       asm volatile("cp.async.wait_group %0;" :: "n"(n) : "memory")
#define LDSM4(r0,r1,r2,r3,a) \
    asm volatile("ldmatrix.sync.aligned.m8n8.x4.shared.b16 {%0,%1,%2,%3}, [%4];" \
        : "=r"(r0),"=r"(r1),"=r"(r2),"=r"(r3) : "r"(a))

// ============================================================================
// Kernel 0: fp32 -> fp16 preconvert of x and Wq/Wk/Wv.
// ============================================================================
__global__ __launch_bounds__(256) void cvt_kernel(
    const float* __restrict__ x, const float* __restrict__ Wk,
    const float* __restrict__ Wq, const float* __restrict__ Wv)
{
    const size_t t = (size_t)blockIdx.x * 256 + threadIdx.x;
    const size_t base = t * 8;
    if (base < (size_t)NBT*NC) {
        float4 f0 = *(const float4*)(x + base);
        float4 f1 = *(const float4*)(x + base + 4);
        *(uint4*)(g_X16 + base) = make_uint4(h2(f0.x,f0.y), h2(f0.z,f0.w),
                                             h2(f1.x,f1.y), h2(f1.z,f1.w));
    }
    if (t < (size_t)3*NH*NC/8) {
        const int w = (int)t * 8;
        const int sec = w / (NH*NC);
        const int off = w - sec * (NH*NC);
        const float* W = (sec == 0) ? Wq : (sec == 1 ? Wk : Wv);
        float4 f0 = *(const float4*)(W + off);
        float4 f1 = *(const float4*)(W + off + 4);
        *(uint4*)(g_Wh[sec] + off) = make_uint4(h2(f0.x,f0.y), h2(f0.z,f0.w),
                                                h2(f1.x,f1.y), h2(f1.z,f1.w));
    }
}

// ============================================================================
// Kernel 1: QKV projection (fp16 in/out). CTA 128x128, k-tile 32,
// 2-stage cp.async pipeline, ldmatrix.x4 fragment loads.
// smem row stride 40 halves (80B): LDSM phases bank-conflict-free (5r mod 8).
// ============================================================================
__global__ __launch_bounds__(256) void proj_kernel()
{
    __shared__ __align__(16) __half As[2][128*40];
    __shared__ __align__(16) __half Bs[2][128*40];

    const int z = blockIdx.z;
    const __half* Xb = g_X16 + (size_t)(blockIdx.x*128)*NC;
    const __half* Wb = g_Wh[z] + (size_t)(blockIdx.y*128)*NC;
    __half* out = (z == 0 ? g_Q : (z == 1 ? g_K : g_V));

    const int m0 = blockIdx.x * 128, n0 = blockIdx.y * 128;
    const int tid  = threadIdx.x;
    const int lane = tid & 31, wid = tid >> 5;
    const int mw = wid & 3, nw = wid >> 2;
    const int g  = lane >> 2, th = lane & 3;

    // fill mapping: thread -> (row, 16-half chunk)
    const int frow = tid >> 1, fco = (tid & 1) * 16;
    // ldmatrix lane address components
    const int arow = mw*32 + ((lane>>3)&1)*8 + (lane&7);
    const int akw  = (lane>>4)*8;
    const int brow = nw*64 + (lane>>4)*8 + (lane&7);
    const int bkw  = ((lane>>3)&1)*8;

    float acc[2][8][4];
    #pragma unroll
    for (int i = 0; i < 2; i++)
        #pragma unroll
        for (int q = 0; q < 8; q++)
            #pragma unroll
            for (int p = 0; p < 4; p++) acc[i][q][p] = 0.f;

    auto issue = [&](int it){
        if (it < 12) {
            const int s = it & 1, k0 = it * 32;
            const __half* gA = Xb + (size_t)frow*NC + k0 + fco;
            const __half* gB = Wb + (size_t)frow*NC + k0 + fco;
            unsigned sA = su32(&As[s][frow*40 + fco]);
            unsigned sB = su32(&Bs[s][frow*40 + fco]);
            CPA(sA,      gA);
            CPA(sA + 16, gA + 8);
            CPA(sB,      gB);
            CPA(sB + 16, gB + 8);
        }
        CPC();
    };

    issue(0);
    issue(1);

    for (int it = 0; it < 12; it++) {
        const int s = it & 1;
        CPW(1);
        __syncthreads();

        #pragma unroll
        for (int ks = 0; ks < 2; ks++) {
            unsigned a0[4], a1[4];
            LDSM4(a0[0],a0[1],a0[2],a0[3], su32(&As[s][ arow     *40 + akw + ks*16]));
            LDSM4(a1[0],a1[1],a1[2],a1[3], su32(&As[s][(arow+16) *40 + akw + ks*16]));
            unsigned b[8][2];
            #pragma unroll
            for (int p = 0; p < 4; p++) {
                unsigned r0,r1,r2,r3;
                LDSM4(r0,r1,r2,r3, su32(&Bs[s][(brow + p*16)*40 + bkw + ks*16]));
                b[2*p  ][0] = r0; b[2*p  ][1] = r1;
                b[2*p+1][0] = r2; b[2*p+1][1] = r3;
            }
            #pragma unroll
            for (int nt = 0; nt < 8; nt++) {
                mma16(acc[0][nt], a0, b[nt]);
                mma16(acc[1][nt], a1, b[nt]);
            }
        }
        __syncthreads();
        issue(it + 2);
    }

    #pragma unroll
    for (int mt = 0; mt < 2; mt++)
        #pragma unroll
        for (int nt = 0; nt < 8; nt++) {
            int row = m0 + mw*32 + mt*16 + g;
            int col = n0 + nw*64 + nt*8 + 2*th;
            *(unsigned*)(out + (size_t)row*NH + col)     = h2(acc[mt][nt][0], acc[mt][nt][1]);
            *(unsigned*)(out + (size_t)(row+8)*NH + col) = h2(acc[mt][nt][2], acc[mt][nt][3]);
        }
}

// ============================================================================
// Kernel 2 (unchanged from R5): S = scale*QK^T causal, softmax -> P fp16.
// ============================================================================
__global__ __launch_bounds__(256) void scores_kernel()
{
    __shared__ __align__(16) unsigned Qs[64][8];
    __shared__ __align__(16) unsigned Ks[256][8];
    __shared__ float redm[2][64];
    __shared__ float reds[2][64];

    const int b = blockIdx.y, bx = blockIdx.x;
    const int qt0 = bx * 64, ncols = (bx + 1) * 64;
    const int tid  = threadIdx.x;
    const int lane = tid & 31, wid = tid >> 5;
    const int mw = wid & 3, nw = wid >> 2;
    const int g  = lane >> 2, th = lane & 3;
    const int base = nw * 128;
    int ntc = (ncols - base) / 8;
    ntc = ntc < 0 ? 0 : (ntc > 16 ? 16 : ntc);

    const __half* Qm = g_Q + (size_t)b * NT * NH;
    const __half* Km = g_K + (size_t)b * NT * NH;

    float acc[16][4];
    #pragma unroll
    for (int i = 0; i < 16; i++)
        #pragma unroll
        for (int p = 0; p < 4; p++) acc[i][p] = 0.f;

    const int lr = tid >> 1, j = tid & 1;
    const __half* pQ = Qm + (size_t)(qt0+lr)*NH + j*8;
    const __half* pK = Km + (size_t)lr*NH + j*8;
    uint4 fq;
    if (tid < 128) fq = *(const uint4*)(pQ);
    uint4 fk0 = *(const uint4*)(pK);
    uint4 fk1 = *(const uint4*)(pK + (size_t)128*NH);

    for (int it = 0; it < NH/16; it++) {
        if (tid < 128) *(uint4*)&Qs[lr][4*j] = fq;
        *(uint4*)&Ks[lr    ][4*j] = fk0;
        *(uint4*)&Ks[lr+128][4*j] = fk1;
        __syncthreads();
        if (it + 1 < NH/16) {
            if (tid < 128) fq = *(const uint4*)(pQ + (it+1)*16);
            fk0 = *(const uint4*)(pK + (it+1)*16);
            fk1 = *(const uint4*)(pK + (size_t)128*NH + (it+1)*16);
        }

        if (ntc > 0) {
            unsigned a[4];
            int row = mw*16;
            a[0] = Qs[row+g  ][th  ];
            a[1] = Qs[row+g+8][th  ];
            a[2] = Qs[row+g  ][th+4];
            a[3] = Qs[row+g+8][th+4];
            #pragma unroll
            for (int nt = 0; nt < 16; nt++) {
                if (nt < ntc) {
                    int col = base + nt*8 + g;
                    unsigned bb[2] = { Ks[col][th], Ks[col][th+4] };
                    mma16(acc[nt], a, bb);
                }
            }
        }
        __syncthreads();
    }

    const float scale = 0.05103103630798288f;  // 384^-0.5
    const int r0 = mw*16 + g, r1 = r0 + 8;
    const int q0 = qt0 + r0, q1 = qt0 + r1;

    float mx0 = NEG_INF, mx1 = NEG_INF;
    #pragma unroll
    for (int nt = 0; nt < 16; nt++) {
        if (nt < ntc) {
            int c = base + nt*8 + 2*th;
            float s00 = (c   <= q0) ? acc[nt][0]*scale : NEG_INF;
            float s01 = (c+1 <= q0) ? acc[nt][1]*scale : NEG_INF;
            float s10 = (c   <= q1) ? acc[nt][2]*scale : NEG_INF;
            float s11 = (c+1 <= q1) ? acc[nt][3]*scale : NEG_INF;
            acc[nt][0]=s00; acc[nt][1]=s01; acc[nt][2]=s10; acc[nt][3]=s11;
            mx0 = fmaxf(mx0, fmaxf(s00, s01));
            mx1 = fmaxf(mx1, fmaxf(s10, s11));
        }
    }
    mx0 = fmaxf(mx0, __shfl_xor_sync(0xffffffffu, mx0, 1));
    mx0 = fmaxf(mx0, __shfl_xor_sync(0xffffffffu, mx0, 2));
    mx1 = fmaxf(mx1, __shfl_xor_sync(0xffffffffu, mx1, 1));
    mx1 = fmaxf(mx1, __shfl_xor_sync(0xffffffffu, mx1, 2));
    if (th == 0) { redm[nw][r0] = mx0; redm[nw][r1] = mx1; }
    __syncthreads();

    float M0 = fmaxf(redm[0][r0], redm[1][r0]);
    float M1 = fmaxf(redm[0][r1], redm[1][r1]);

    float sm0 = 0.f, sm1 = 0.f;
    #pragma unroll
    for (int nt = 0; nt < 16; nt++) {
        if (nt < ntc) {
            float e00 = __expf(acc[nt][0] - M0);
            float e01 = __expf(acc[nt][1] - M0);
            float e10 = __expf(acc[nt][2] - M1);
            float e11 = __expf(acc[nt][3] - M1);
            acc[nt][0]=e00; acc[nt][1]=e01; acc[nt][2]=e10; acc[nt][3]=e11;
            sm0 += e00 + e01; sm1 += e10 + e11;
        }
    }
    sm0 += __shfl_xor_sync(0xffffffffu, sm0, 1);
    sm0 += __shfl_xor_sync(0xffffffffu, sm0, 2);
    sm1 += __shfl_xor_sync(0xffffffffu, sm1, 1);
    sm1 += __shfl_xor_sync(0xffffffffu, sm1, 2);
    if (th == 0) { reds[nw][r0] = sm0; reds[nw][r1] = sm1; }
    __syncthreads();

    float inv0 = 1.f / (reds[0][r0] + reds[1][r0]);
    float inv1 = 1.f / (reds[0][r1] + reds[1][r1]);

    __half* Pb = g_P + (size_t)b * NT * NT;
    #pragma unroll
    for (int nt = 0; nt < 16; nt++) {
        if (nt < ntc) {
            int c = base + nt*8 + 2*th;
            *(unsigned*)(Pb + (size_t)q0*NT + c) = h2(acc[nt][0]*inv0, acc[nt][1]*inv0);
            *(unsigned*)(Pb + (size_t)q1*NT + c) = h2(acc[nt][2]*inv1, acc[nt][3]*inv1);
        }
    }

    const int width = 256 - ncols;
    if (width > 0) {
        const int w8 = width >> 3;
        const uint4 zz = make_uint4(0,0,0,0);
        for (int i = tid; i < 64 * w8; i += 256) {
            int row = i / w8, cc = ncols + (i - row*w8)*8;
            *(uint4*)(Pb + (size_t)(qt0+row)*NT + cc) = zz;
        }
    }
}

// ============================================================================
// Kernel 3 (unchanged from R5): O = P @ V per batch (fp32 out).
// ============================================================================
__global__ __launch_bounds__(256) void pv_kernel(float* __restrict__ out)
{
    __shared__ __align__(16) unsigned Ps[128][8];
    __shared__ __align__(16) unsigned Vs2[8][136];

    const int b  = blockIdx.z;
    const int m0 = blockIdx.x * 128, n0 = blockIdx.y * 128;
    const int tid  = threadIdx.x;
    const int lane = tid & 31, wid = tid >> 5;
    const int mw = wid & 3, nw = wid >> 2;
    const int g  = lane >> 2, th = lane & 3;
    const int lr = tid >> 1, j = tid & 1;
    const int vp = tid >> 5, vl = tid & 31;
    const int nit = (m0 + 128) / 16;

    const __half* Pm = g_P + (size_t)b * NT * NT;
    const __half* Vm = g_V + (size_t)b * NT * NH;

    float acc[2][8][4];
    #pragma unroll
    for (int i = 0; i < 2; i++)
        #pragma unroll
        for (int q = 0; q < 8; q++)
            #pragma unroll
            for (int p = 0; p < 4; p++) acc[i][q][p] = 0.f;

    const __half* pP = Pm + (size_t)(m0+lr)*NT + j*8;
    const __half* pV = Vm + (size_t)(2*vp)*NH + n0 + 4*vl;
    uint4 fp = *(const uint4*)(pP);
    uint2 fv0 = *(const uint2*)(pV);
    uint2 fv1 = *(const uint2*)(pV + NH);

    for (int it = 0; it < nit; it++) {
        *(uint4*)&Ps[lr][4*j] = fp;
        *(uint4*)&Vs2[vp][4*vl] = make_uint4(
            __byte_perm(fv0.x, fv1.x, 0x5410), __byte_perm(fv0.x, fv1.x, 0x7632),
            __byte_perm(fv0.y, fv1.y, 0x5410), __byte_perm(fv0.y, fv1.y, 0x7632));
        __syncthreads();
        if (it + 1 < nit) {
            fp  = *(const uint4*)(pP + (it+1)*16);
            fv0 = *(const uint2*)(pV + (size_t)(it+1)*16*NH);
            fv1 = *(const uint2*)(pV + (size_t)(it+1)*16*NH + NH);
        }

        unsigned a[2][4];
        #pragma unroll
        for (int mt = 0; mt < 2; mt++) {
            int row = mw*32 + mt*16;
            a[mt][0] = Ps[row+g  ][th  ];
            a[mt][1] = Ps[row+g+8][th  ];
            a[mt][2] = Ps[row+g  ][th+4];
            a[mt][3] = Ps[row+g+8][th+4];
        }
        #pragma unroll
        for (int nt = 0; nt < 8; nt++) {
            int col = nw*64 + nt*8 + g;
            unsigned bb[2] = { Vs2[th][col], Vs2[th+4][col] };
            mma16(acc[0][nt], a[0], bb);
            mma16(acc[1][nt], a[1], bb);
        }
        __syncthreads();
    }

    #pragma unroll
    for (int mt = 0; mt < 2; mt++)
        #pragma unroll
        for (int nt = 0; nt < 8; nt++) {
            int row = m0 + mw*32 + mt*16 + g;
            int col = n0 + nw*64 + nt*8 + 2*th;
            size_t base_o = (size_t)(b*NT + row) * NH + col;
            *(float2*)(out + base_o)                = make_float2(acc[mt][nt][0], acc[mt][nt][1]);
            *(float2*)(out + base_o + (size_t)8*NH) = make_float2(acc[mt][nt][2], acc[mt][nt][3]);
        }
}

// ============================================================================
extern "C" void kernel_launch(void* const* d_in, const int* in_sizes, int n_in,
                              void* d_out, int out_size)
{
    const float* x  = (const float*)d_in[0];
    const float* Wk = (const float*)d_in[1];
    const float* Wq = (const float*)d_in[2];
    const float* Wv = (const float*)d_in[3];
    float* out = (float*)d_out;

    cvt_kernel   <<<((NBT*NC/8) + 255) / 256, 256>>>(x, Wk, Wq, Wv);
    proj_kernel  <<<dim3(NBT/128, NH/128, 3), 256>>>();
    scores_kernel<<<dim3(NT/64,  NB),         256>>>();
    pv_kernel    <<<dim3(NT/128, NH/128, NB), 256>>>(out);
}

// round 7
// speedup vs baseline: 10.6758x; 1.0860x over previous
#include <cuda_runtime.h>
#include <cuda_fp16.h>
#include <cstdint>

#define NB 256
#define NT 256
#define NC 384
#define NH 384
#define NBT (NB*NT)

__device__ __half g_X16[(size_t)NBT*NC];
__device__ __half g_Wh[3][(size_t)NH*NC];
__device__ __half g_Q[(size_t)NBT*NH];
__device__ __half g_K[(size_t)NBT*NH];
__device__ __half g_V[(size_t)NBT*NH];
__device__ __half g_P[(size_t)NB*NT*NT];

#define NEG_INF (__int_as_float((int)0xff800000))

__forceinline__ __device__ unsigned h2(float a, float b){
    __half2 h = __floats2half2_rn(a, b);
    return *reinterpret_cast<unsigned*>(&h);
}
__forceinline__ __device__ void mma16(float* c, const unsigned* a, const unsigned* b){
    asm("mma.sync.aligned.m16n8k16.row.col.f32.f16.f16.f32 "
        "{%0,%1,%2,%3}, {%4,%5,%6,%7}, {%8,%9}, {%0,%1,%2,%3};"
        : "+f"(c[0]), "+f"(c[1]), "+f"(c[2]), "+f"(c[3])
        : "r"(a[0]), "r"(a[1]), "r"(a[2]), "r"(a[3]), "r"(b[0]), "r"(b[1]));
}
__forceinline__ __device__ unsigned su32(const void* p){
    return (unsigned)__cvta_generic_to_shared(p);
}
#define CPA(dst,src) asm volatile("cp.async.ca.shared.global [%0], [%1], 16;" :: "r"(dst), "l"(src) : "memory")
#define CPC()        asm volatile("cp.async.commit_group;" ::: "memory")
#define CPW(n)       asm volatile("cp.async.wait_group %0;" :: "n"(n) : "memory")
#define LDSM4(r0,r1,r2,r3,a) \
    asm volatile("ldmatrix.sync.aligned.m8n8.x4.shared.b16 {%0,%1,%2,%3}, [%4];" \
        : "=r"(r0),"=r"(r1),"=r"(r2),"=r"(r3) : "r"(a))
#define LDSM4T(r0,r1,r2,r3,a) \
    asm volatile("ldmatrix.sync.aligned.m8n8.x4.trans.shared.b16 {%0,%1,%2,%3}, [%4];" \
        : "=r"(r0),"=r"(r1),"=r"(r2),"=r"(r3) : "r"(a))

// ============================================================================
// Kernel 0: fp32 -> fp16 preconvert of x and Wq/Wk/Wv.
// ============================================================================
__global__ __launch_bounds__(256) void cvt_kernel(
    const float* __restrict__ x, const float* __restrict__ Wk,
    const float* __restrict__ Wq, const float* __restrict__ Wv)
{
    const size_t t = (size_t)blockIdx.x * 256 + threadIdx.x;
    const size_t base = t * 8;
    if (base < (size_t)NBT*NC) {
        float4 f0 = *(const float4*)(x + base);
        float4 f1 = *(const float4*)(x + base + 4);
        *(uint4*)(g_X16 + base) = make_uint4(h2(f0.x,f0.y), h2(f0.z,f0.w),
                                             h2(f1.x,f1.y), h2(f1.z,f1.w));
    }
    if (t < (size_t)3*NH*NC/8) {
        const int w = (int)t * 8;
        const int sec = w / (NH*NC);
        const int off = w - sec * (NH*NC);
        const float* W = (sec == 0) ? Wq : (sec == 1 ? Wk : Wv);
        float4 f0 = *(const float4*)(W + off);
        float4 f1 = *(const float4*)(W + off + 4);
        *(uint4*)(g_Wh[sec] + off) = make_uint4(h2(f0.x,f0.y), h2(f0.z,f0.w),
                                                h2(f1.x,f1.y), h2(f1.z,f1.w));
    }
}

// ============================================================================
// Kernel 1 (unchanged from R6): QKV projection, cp.async + ldmatrix.
// ============================================================================
__global__ __launch_bounds__(256) void proj_kernel()
{
    __shared__ __align__(16) __half As[2][128*40];
    __shared__ __align__(16) __half Bs[2][128*40];

    const int z = blockIdx.z;
    const __half* Xb = g_X16 + (size_t)(blockIdx.x*128)*NC;
    const __half* Wb = g_Wh[z] + (size_t)(blockIdx.y*128)*NC;
    __half* out = (z == 0 ? g_Q : (z == 1 ? g_K : g_V));

    const int m0 = blockIdx.x * 128, n0 = blockIdx.y * 128;
    const int tid  = threadIdx.x;
    const int lane = tid & 31, wid = tid >> 5;
    const int mw = wid & 3, nw = wid >> 2;
    const int g  = lane >> 2, th = lane & 3;

    const int frow = tid >> 1, fco = (tid & 1) * 16;
    const int arow = mw*32 + ((lane>>3)&1)*8 + (lane&7);
    const int akw  = (lane>>4)*8;
    const int brow = nw*64 + (lane>>4)*8 + (lane&7);
    const int bkw  = ((lane>>3)&1)*8;

    float acc[2][8][4];
    #pragma unroll
    for (int i = 0; i < 2; i++)
        #pragma unroll
        for (int q = 0; q < 8; q++)
            #pragma unroll
            for (int p = 0; p < 4; p++) acc[i][q][p] = 0.f;

    auto issue = [&](int it){
        if (it < 12) {
            const int s = it & 1, k0 = it * 32;
            const __half* gA = Xb + (size_t)frow*NC + k0 + fco;
            const __half* gB = Wb + (size_t)frow*NC + k0 + fco;
            unsigned sA = su32(&As[s][frow*40 + fco]);
            unsigned sB = su32(&Bs[s][frow*40 + fco]);
            CPA(sA,      gA);
            CPA(sA + 16, gA + 8);
            CPA(sB,      gB);
            CPA(sB + 16, gB + 8);
        }
        CPC();
    };

    issue(0);
    issue(1);

    for (int it = 0; it < 12; it++) {
        const int s = it & 1;
        CPW(1);
        __syncthreads();

        #pragma unroll
        for (int ks = 0; ks < 2; ks++) {
            unsigned a0[4], a1[4];
            LDSM4(a0[0],a0[1],a0[2],a0[3], su32(&As[s][ arow     *40 + akw + ks*16]));
            LDSM4(a1[0],a1[1],a1[2],a1[3], su32(&As[s][(arow+16) *40 + akw + ks*16]));
            unsigned b[8][2];
            #pragma unroll
            for (int p = 0; p < 4; p++) {
                unsigned r0,r1,r2,r3;
                LDSM4(r0,r1,r2,r3, su32(&Bs[s][(brow + p*16)*40 + bkw + ks*16]));
                b[2*p  ][0] = r0; b[2*p  ][1] = r1;
                b[2*p+1][0] = r2; b[2*p+1][1] = r3;
            }
            #pragma unroll
            for (int nt = 0; nt < 8; nt++) {
                mma16(acc[0][nt], a0, b[nt]);
                mma16(acc[1][nt], a1, b[nt]);
            }
        }
        __syncthreads();
        issue(it + 2);
    }

    #pragma unroll
    for (int mt = 0; mt < 2; mt++)
        #pragma unroll
        for (int nt = 0; nt < 8; nt++) {
            int row = m0 + mw*32 + mt*16 + g;
            int col = n0 + nw*64 + nt*8 + 2*th;
            *(unsigned*)(out + (size_t)row*NH + col)     = h2(acc[mt][nt][0], acc[mt][nt][1]);
            *(unsigned*)(out + (size_t)(row+8)*NH + col) = h2(acc[mt][nt][2], acc[mt][nt][3]);
        }
}

// ============================================================================
// Kernel 2: S = scale*QK^T causal, softmax -> P fp16.
// k-tile 16, 2-stage cp.async, ldmatrix fragments. Row stride 24 halves
// (bank walk 12r mod 32 — conflict-free).
// ============================================================================
__global__ __launch_bounds__(256) void scores_kernel()
{
    __shared__ __align__(16) __half Qs[2][64*24];
    __shared__ __align__(16) __half Ks[2][256*24];
    __shared__ float redm[2][64];
    __shared__ float reds[2][64];

    const int b = blockIdx.y, bx = blockIdx.x;
    const int qt0 = bx * 64, ncols = (bx + 1) * 64;
    const int tid  = threadIdx.x;
    const int lane = tid & 31, wid = tid >> 5;
    const int mw = wid & 3, nw = wid >> 2;
    const int g  = lane >> 2, th = lane & 3;
    const int base = nw * 128;
    int ntc = (ncols - base) / 8;
    ntc = ntc < 0 ? 0 : (ntc > 16 ? 16 : ntc);

    const __half* Qm = g_Q + (size_t)b * NT * NH;
    const __half* Km = g_K + (size_t)b * NT * NH;

    // ldmatrix lane address components (validated in proj)
    const int aro = ((lane>>3)&1)*8 + (lane&7);
    const int akw = (lane>>4)*8;
    const int bro = (lane>>4)*8 + (lane&7);
    const int bkw = ((lane>>3)&1)*8;

    float acc[16][4];
    #pragma unroll
    for (int i = 0; i < 16; i++)
        #pragma unroll
        for (int p = 0; p < 4; p++) acc[i][p] = 0.f;

    const int qr = tid >> 1, qo = (tid & 1) * 8;
    auto issue = [&](int it){
        if (it < NH/16) {
            const int s = it & 1, k0 = it * 16;
            unsigned sK = su32(&Ks[s][tid*24]);
            const __half* gK = Km + (size_t)tid*NH + k0;
            CPA(sK,      gK);
            CPA(sK + 16, gK + 8);
            if (tid < 128)
                CPA(su32(&Qs[s][qr*24 + qo]), Qm + (size_t)(qt0+qr)*NH + k0 + qo);
        }
        CPC();
    };

    issue(0);
    issue(1);

    for (int it = 0; it < NH/16; it++) {
        const int s = it & 1;
        CPW(1);
        __syncthreads();

        if (ntc > 0) {
            unsigned a[4];
            LDSM4(a[0],a[1],a[2],a[3], su32(&Qs[s][(mw*16 + aro)*24 + akw]));
            #pragma unroll
            for (int p = 0; p < 8; p++) {
                if (2*p < ntc) {
                    unsigned r0,r1,r2,r3;
                    LDSM4(r0,r1,r2,r3, su32(&Ks[s][(base + p*16 + bro)*24 + bkw]));
                    unsigned b0[2] = {r0, r1}, b1[2] = {r2, r3};
                    mma16(acc[2*p], a, b0);
                    if (2*p+1 < ntc) mma16(acc[2*p+1], a, b1);
                }
            }
        }
        __syncthreads();
        issue(it + 2);
    }

    const float scale = 0.05103103630798288f;  // 384^-0.5
    const int r0 = mw*16 + g, r1 = r0 + 8;
    const int q0 = qt0 + r0, q1 = qt0 + r1;

    float mx0 = NEG_INF, mx1 = NEG_INF;
    #pragma unroll
    for (int nt = 0; nt < 16; nt++) {
        if (nt < ntc) {
            int c = base + nt*8 + 2*th;
            float s00 = (c   <= q0) ? acc[nt][0]*scale : NEG_INF;
            float s01 = (c+1 <= q0) ? acc[nt][1]*scale : NEG_INF;
            float s10 = (c   <= q1) ? acc[nt][2]*scale : NEG_INF;
            float s11 = (c+1 <= q1) ? acc[nt][3]*scale : NEG_INF;
            acc[nt][0]=s00; acc[nt][1]=s01; acc[nt][2]=s10; acc[nt][3]=s11;
            mx0 = fmaxf(mx0, fmaxf(s00, s01));
            mx1 = fmaxf(mx1, fmaxf(s10, s11));
        }
    }
    mx0 = fmaxf(mx0, __shfl_xor_sync(0xffffffffu, mx0, 1));
    mx0 = fmaxf(mx0, __shfl_xor_sync(0xffffffffu, mx0, 2));
    mx1 = fmaxf(mx1, __shfl_xor_sync(0xffffffffu, mx1, 1));
    mx1 = fmaxf(mx1, __shfl_xor_sync(0xffffffffu, mx1, 2));
    if (th == 0) { redm[nw][r0] = mx0; redm[nw][r1] = mx1; }
    __syncthreads();

    float M0 = fmaxf(redm[0][r0], redm[1][r0]);
    float M1 = fmaxf(redm[0][r1], redm[1][r1]);

    float sm0 = 0.f, sm1 = 0.f;
    #pragma unroll
    for (int nt = 0; nt < 16; nt++) {
        if (nt < ntc) {
            float e00 = __expf(acc[nt][0] - M0);
            float e01 = __expf(acc[nt][1] - M0);
            float e10 = __expf(acc[nt][2] - M1);
            float e11 = __expf(acc[nt][3] - M1);
            acc[nt][0]=e00; acc[nt][1]=e01; acc[nt][2]=e10; acc[nt][3]=e11;
            sm0 += e00 + e01; sm1 += e10 + e11;
        }
    }
    sm0 += __shfl_xor_sync(0xffffffffu, sm0, 1);
    sm0 += __shfl_xor_sync(0xffffffffu, sm0, 2);
    sm1 += __shfl_xor_sync(0xffffffffu, sm1, 1);
    sm1 += __shfl_xor_sync(0xffffffffu, sm1, 2);
    if (th == 0) { reds[nw][r0] = sm0; reds[nw][r1] = sm1; }
    __syncthreads();

    float inv0 = 1.f / (reds[0][r0] + reds[1][r0]);
    float inv1 = 1.f / (reds[0][r1] + reds[1][r1]);

    __half* Pb = g_P + (size_t)b * NT * NT;
    #pragma unroll
    for (int nt = 0; nt < 16; nt++) {
        if (nt < ntc) {
            int c = base + nt*8 + 2*th;
            *(unsigned*)(Pb + (size_t)q0*NT + c) = h2(acc[nt][0]*inv0, acc[nt][1]*inv0);
            *(unsigned*)(Pb + (size_t)q1*NT + c) = h2(acc[nt][2]*inv1, acc[nt][3]*inv1);
        }
    }

    const int width = 256 - ncols;
    if (width > 0) {
        const int w8 = width >> 3;
        const uint4 zz = make_uint4(0,0,0,0);
        for (int i = tid; i < 64 * w8; i += 256) {
            int row = i / w8, cc = ncols + (i - row*w8)*8;
            *(uint4*)(Pb + (size_t)(qt0+row)*NT + cc) = zz;
        }
    }
}

// ============================================================================
// Kernel 3: O = P @ V (fp32 out). k-tile 32, 2-stage cp.async.
// P frags via ldmatrix.x4; V natural [k][n] rows, frags via ldmatrix.x4.trans
// (stride 136 halves: trans phases hit banks 4r+c — conflict-free).
// ============================================================================
__global__ __launch_bounds__(256) void pv_kernel(float* __restrict__ out)
{
    __shared__ __align__(16) __half Ps[2][128*40];
    __shared__ __align__(16) __half Vs[2][32*136];

    const int b  = blockIdx.z;
    const int m0 = blockIdx.x * 128, n0 = blockIdx.y * 128;
    const int tid  = threadIdx.x;
    const int lane = tid & 31, wid = tid >> 5;
    const int mw = wid & 3, nw = wid >> 2;
    const int g  = lane >> 2, th = lane & 3;
    const int nit = (m0 + 128) / 32;       // causal: 4 or 8 k32-tiles

    const __half* Pm = g_P + (size_t)b * NT * NT;
    const __half* Vm = g_V + (size_t)b * NT * NH;

    const int prow = tid >> 1, pco = (tid & 1) * 16;   // P fill
    const int vrow = tid >> 3, vco = (tid & 7) * 16;   // V fill
    const int aro = ((lane>>3)&1)*8 + (lane&7);
    const int akw = (lane>>4)*8;
    const int tro = (lane&7) + ((lane>>3)&1)*8;        // trans: k-row within tile
    const int tno = (lane>>4)*8;                       // trans: n-offset

    float acc[2][8][4];
    #pragma unroll
    for (int i = 0; i < 2; i++)
        #pragma unroll
        for (int q = 0; q < 8; q++)
            #pragma unroll
            for (int p = 0; p < 4; p++) acc[i][q][p] = 0.f;

    auto issue = [&](int it){
        if (it < nit) {
            const int s = it & 1, k0 = it * 32;
            unsigned sP = su32(&Ps[s][prow*40 + pco]);
            const __half* gP = Pm + (size_t)(m0+prow)*NT + k0 + pco;
            CPA(sP,      gP);
            CPA(sP + 16, gP + 8);
            unsigned sV = su32(&Vs[s][vrow*136 + vco]);
            const __half* gV = Vm + (size_t)(k0+vrow)*NH + n0 + vco;
            CPA(sV,      gV);
            CPA(sV + 16, gV + 8);
        }
        CPC();
    };

    issue(0);
    issue(1);

    for (int it = 0; it < nit; it++) {
        const int s = it & 1;
        CPW(1);
        __syncthreads();

        #pragma unroll
        for (int ks = 0; ks < 2; ks++) {
            unsigned a0[4], a1[4];
            LDSM4(a0[0],a0[1],a0[2],a0[3], su32(&Ps[s][(mw*32      + aro)*40 + akw + ks*16]));
            LDSM4(a1[0],a1[1],a1[2],a1[3], su32(&Ps[s][(mw*32 + 16 + aro)*40 + akw + ks*16]));
            unsigned bb[8][2];
            #pragma unroll
            for (int c2 = 0; c2 < 4; c2++) {
                unsigned r0,r1,r2,r3;
                LDSM4T(r0,r1,r2,r3,
                    su32(&Vs[s][(ks*16 + tro)*136 + nw*64 + c2*16 + tno]));
                bb[2*c2  ][0] = r0; bb[2*c2  ][1] = r1;
                bb[2*c2+1][0] = r2; bb[2*c2+1][1] = r3;
            }
            #pragma unroll
            for (int nt = 0; nt < 8; nt++) {
                mma16(acc[0][nt], a0, bb[nt]);
                mma16(acc[1][nt], a1, bb[nt]);
            }
        }
        __syncthreads();
        issue(it + 2);
    }

    #pragma unroll
    for (int mt = 0; mt < 2; mt++)
        #pragma unroll
        for (int nt = 0; nt < 8; nt++) {
            int row = m0 + mw*32 + mt*16 + g;
            int col = n0 + nw*64 + nt*8 + 2*th;
            size_t base_o = (size_t)(b*NT + row) * NH + col;
            *(float2*)(out + base_o)                = make_float2(acc[mt][nt][0], acc[mt][nt][1]);
            *(float2*)(out + base_o + (size_t)8*NH) = make_float2(acc[mt][nt][2], acc[mt][nt][3]);
        }
}

// ============================================================================
extern "C" void kernel_launch(void* const* d_in, const int* in_sizes, int n_in,
                              void* d_out, int out_size)
{
    const float* x  = (const float*)d_in[0];
    const float* Wk = (const float*)d_in[1];
    const float* Wq = (const float*)d_in[2];
    const float* Wv = (const float*)d_in[3];
    float* out = (float*)d_out;

    cvt_kernel   <<<((NBT*NC/8) + 255) / 256, 256>>>(x, Wk, Wq, Wv);
    proj_kernel  <<<dim3(NBT/128, NH/128, 3), 256>>>();
    scores_kernel<<<dim3(NT/64,  NB),         256>>>();
    pv_kernel    <<<dim3(NT/128, NH/128, NB), 256>>>(out);
}

// round 8
// speedup vs baseline: 10.7093x; 1.0031x over previous
#include <cuda_runtime.h>
#include <cuda_fp16.h>
#include <cstdint>

#define NB 256
#define NT 256
#define NC 384
#define NH 384
#define NBT (NB*NT)

__device__ __half g_X16[(size_t)NBT*NC];
__device__ __half g_Wh[3][(size_t)NH*NC];
__device__ __half g_Q[(size_t)NBT*NH];
__device__ __half g_K[(size_t)NBT*NH];
__device__ __half g_V[(size_t)NBT*NH];
__device__ __half g_P[(size_t)NB*NT*NT];

#define NEG_INF (__int_as_float((int)0xff800000))

__forceinline__ __device__ unsigned h2(float a, float b){
    __half2 h = __floats2half2_rn(a, b);
    return *reinterpret_cast<unsigned*>(&h);
}
__forceinline__ __device__ void mma16(float* c, const unsigned* a, const unsigned* b){
    asm("mma.sync.aligned.m16n8k16.row.col.f32.f16.f16.f32 "
        "{%0,%1,%2,%3}, {%4,%5,%6,%7}, {%8,%9}, {%0,%1,%2,%3};"
        : "+f"(c[0]), "+f"(c[1]), "+f"(c[2]), "+f"(c[3])
        : "r"(a[0]), "r"(a[1]), "r"(a[2]), "r"(a[3]), "r"(b[0]), "r"(b[1]));
}
__forceinline__ __device__ unsigned su32(const void* p){
    return (unsigned)__cvta_generic_to_shared(p);
}
#define CPA(dst,src) asm volatile("cp.async.ca.shared.global [%0], [%1], 16;" :: "r"(dst), "l"(src) : "memory")
#define CPC()        asm volatile("cp.async.commit_group;" ::: "memory")
#define CPW(n)       asm volatile("cp.async.wait_group %0;" :: "n"(n) : "memory")
#define LDSM4(r0,r1,r2,r3,a) \
    asm volatile("ldmatrix.sync.aligned.m8n8.x4.shared.b16 {%0,%1,%2,%3}, [%4];" \
        : "=r"(r0),"=r"(r1),"=r"(r2),"=r"(r3) : "r"(a))
#define LDSM4T(r0,r1,r2,r3,a) \
    asm volatile("ldmatrix.sync.aligned.m8n8.x4.trans.shared.b16 {%0,%1,%2,%3}, [%4];" \
        : "=r"(r0),"=r"(r1),"=r"(r2),"=r"(r3) : "r"(a))

// ============================================================================
// Kernel 0: fp32 -> fp16 preconvert of x and Wq/Wk/Wv.
// ============================================================================
__global__ __launch_bounds__(256) void cvt_kernel(
    const float* __restrict__ x, const float* __restrict__ Wk,
    const float* __restrict__ Wq, const float* __restrict__ Wv)
{
    const size_t t = (size_t)blockIdx.x * 256 + threadIdx.x;
    const size_t base = t * 8;
    if (base < (size_t)NBT*NC) {
        float4 f0 = *(const float4*)(x + base);
        float4 f1 = *(const float4*)(x + base + 4);
        *(uint4*)(g_X16 + base) = make_uint4(h2(f0.x,f0.y), h2(f0.z,f0.w),
                                             h2(f1.x,f1.y), h2(f1.z,f1.w));
    }
    if (t < (size_t)3*NH*NC/8) {
        const int w = (int)t * 8;
        const int sec = w / (NH*NC);
        const int off = w - sec * (NH*NC);
        const float* W = (sec == 0) ? Wq : (sec == 1 ? Wk : Wv);
        float4 f0 = *(const float4*)(W + off);
        float4 f1 = *(const float4*)(W + off + 4);
        *(uint4*)(g_Wh[sec] + off) = make_uint4(h2(f0.x,f0.y), h2(f0.z,f0.w),
                                                h2(f1.x,f1.y), h2(f1.z,f1.w));
    }
}

// ============================================================================
// Kernel 1: QKV projection. 3-stage cp.async pipeline, single barrier/k-tile.
// Dynamic smem: As 3x(128x40) then Bs 3x(128x40) halves.
// ============================================================================
#define PROJ_SMEM (3*(128*40)*2*2)   // 61440 B
__global__ __launch_bounds__(256) void proj_kernel()
{
    extern __shared__ __align__(16) __half dsm[];
    __half* As = dsm;            // stage stride 5120 halves
    __half* Bs = dsm + 15360;

    const int z = blockIdx.z;
    const __half* Xb = g_X16 + (size_t)(blockIdx.x*128)*NC;
    const __half* Wb = g_Wh[z] + (size_t)(blockIdx.y*128)*NC;
    __half* out = (z == 0 ? g_Q : (z == 1 ? g_K : g_V));

    const int m0 = blockIdx.x * 128, n0 = blockIdx.y * 128;
    const int tid  = threadIdx.x;
    const int lane = tid & 31, wid = tid >> 5;
    const int mw = wid & 3, nw = wid >> 2;
    const int g  = lane >> 2, th = lane & 3;

    const int frow = tid >> 1, fco = (tid & 1) * 16;
    const int arow = mw*32 + ((lane>>3)&1)*8 + (lane&7);
    const int akw  = (lane>>4)*8;
    const int brow = nw*64 + (lane>>4)*8 + (lane&7);
    const int bkw  = ((lane>>3)&1)*8;

    float acc[2][8][4];
    #pragma unroll
    for (int i = 0; i < 2; i++)
        #pragma unroll
        for (int q = 0; q < 8; q++)
            #pragma unroll
            for (int p = 0; p < 4; p++) acc[i][q][p] = 0.f;

    auto issue = [&](int it, int st){
        if (it < 12) {
            const int k0 = it * 32;
            const __half* gA = Xb + (size_t)frow*NC + k0 + fco;
            const __half* gB = Wb + (size_t)frow*NC + k0 + fco;
            unsigned sA = su32(As + st*5120 + frow*40 + fco);
            unsigned sB = su32(Bs + st*5120 + frow*40 + fco);
            CPA(sA,      gA);
            CPA(sA + 16, gA + 8);
            CPA(sB,      gB);
            CPA(sB + 16, gB + 8);
        }
        CPC();
    };

    issue(0, 0);
    issue(1, 1);

    int rs = 0;
    for (int it = 0; it < 12; it++) {
        CPW(1);
        __syncthreads();
        int ws = rs + 2; if (ws >= 3) ws -= 3;
        issue(it + 2, ws);

        const __half* Asr = As + rs*5120;
        const __half* Bsr = Bs + rs*5120;
        #pragma unroll
        for (int ks = 0; ks < 2; ks++) {
            unsigned a0[4], a1[4];
            LDSM4(a0[0],a0[1],a0[2],a0[3], su32(Asr +  arow     *40 + akw + ks*16));
            LDSM4(a1[0],a1[1],a1[2],a1[3], su32(Asr + (arow+16) *40 + akw + ks*16));
            unsigned b[8][2];
            #pragma unroll
            for (int p = 0; p < 4; p++) {
                unsigned r0,r1,r2,r3;
                LDSM4(r0,r1,r2,r3, su32(Bsr + (brow + p*16)*40 + bkw + ks*16));
                b[2*p  ][0] = r0; b[2*p  ][1] = r1;
                b[2*p+1][0] = r2; b[2*p+1][1] = r3;
            }
            #pragma unroll
            for (int nt = 0; nt < 8; nt++) {
                mma16(acc[0][nt], a0, b[nt]);
                mma16(acc[1][nt], a1, b[nt]);
            }
        }
        rs = rs + 1; if (rs >= 3) rs -= 3;
    }

    #pragma unroll
    for (int mt = 0; mt < 2; mt++)
        #pragma unroll
        for (int nt = 0; nt < 8; nt++) {
            int row = m0 + mw*32 + mt*16 + g;
            int col = n0 + nw*64 + nt*8 + 2*th;
            *(unsigned*)(out + (size_t)row*NH + col)     = h2(acc[mt][nt][0], acc[mt][nt][1]);
            *(unsigned*)(out + (size_t)(row+8)*NH + col) = h2(acc[mt][nt][2], acc[mt][nt][3]);
        }
}

// ============================================================================
// Kernel 2: S = scale*QK^T causal, softmax -> P fp16.
// 3-stage cp.async, single barrier per k16-tile. Static smem (47KB).
// ============================================================================
__global__ __launch_bounds__(256) void scores_kernel()
{
    __shared__ __align__(16) __half Qs[3][64*24];
    __shared__ __align__(16) __half Ks[3][256*24];
    __shared__ float redm[2][64];
    __shared__ float reds[2][64];

    const int b = blockIdx.y, bx = blockIdx.x;
    const int qt0 = bx * 64, ncols = (bx + 1) * 64;
    const int tid  = threadIdx.x;
    const int lane = tid & 31, wid = tid >> 5;
    const int mw = wid & 3, nw = wid >> 2;
    const int g  = lane >> 2, th = lane & 3;
    const int base = nw * 128;
    int ntc = (ncols - base) / 8;
    ntc = ntc < 0 ? 0 : (ntc > 16 ? 16 : ntc);

    const __half* Qm = g_Q + (size_t)b * NT * NH;
    const __half* Km = g_K + (size_t)b * NT * NH;

    const int aro = ((lane>>3)&1)*8 + (lane&7);
    const int akw = (lane>>4)*8;
    const int bro = (lane>>4)*8 + (lane&7);
    const int bkw = ((lane>>3)&1)*8;

    float acc[16][4];
    #pragma unroll
    for (int i = 0; i < 16; i++)
        #pragma unroll
        for (int p = 0; p < 4; p++) acc[i][p] = 0.f;

    const int qr = tid >> 1, qo = (tid & 1) * 8;
    auto issue = [&](int it, int st){
        if (it < NH/16) {
            const int k0 = it * 16;
            unsigned sK = su32(&Ks[st][tid*24]);
            const __half* gK = Km + (size_t)tid*NH + k0;
            CPA(sK,      gK);
            CPA(sK + 16, gK + 8);
            if (tid < 128)
                CPA(su32(&Qs[st][qr*24 + qo]), Qm + (size_t)(qt0+qr)*NH + k0 + qo);
        }
        CPC();
    };

    issue(0, 0);
    issue(1, 1);

    int rs = 0;
    for (int it = 0; it < NH/16; it++) {
        CPW(1);
        __syncthreads();
        int ws = rs + 2; if (ws >= 3) ws -= 3;
        issue(it + 2, ws);

        if (ntc > 0) {
            unsigned a[4];
            LDSM4(a[0],a[1],a[2],a[3], su32(&Qs[rs][(mw*16 + aro)*24 + akw]));
            #pragma unroll
            for (int p = 0; p < 8; p++) {
                if (2*p < ntc) {
                    unsigned r0,r1,r2,r3;
                    LDSM4(r0,r1,r2,r3, su32(&Ks[rs][(base + p*16 + bro)*24 + bkw]));
                    unsigned b0[2] = {r0, r1}, b1[2] = {r2, r3};
                    mma16(acc[2*p], a, b0);
                    if (2*p+1 < ntc) mma16(acc[2*p+1], a, b1);
                }
            }
        }
        rs = rs + 1; if (rs >= 3) rs -= 3;
    }

    const float scale = 0.05103103630798288f;  // 384^-0.5
    const int r0 = mw*16 + g, r1 = r0 + 8;
    const int q0 = qt0 + r0, q1 = qt0 + r1;

    float mx0 = NEG_INF, mx1 = NEG_INF;
    #pragma unroll
    for (int nt = 0; nt < 16; nt++) {
        if (nt < ntc) {
            int c = base + nt*8 + 2*th;
            float s00 = (c   <= q0) ? acc[nt][0]*scale : NEG_INF;
            float s01 = (c+1 <= q0) ? acc[nt][1]*scale : NEG_INF;
            float s10 = (c   <= q1) ? acc[nt][2]*scale : NEG_INF;
            float s11 = (c+1 <= q1) ? acc[nt][3]*scale : NEG_INF;
            acc[nt][0]=s00; acc[nt][1]=s01; acc[nt][2]=s10; acc[nt][3]=s11;
            mx0 = fmaxf(mx0, fmaxf(s00, s01));
            mx1 = fmaxf(mx1, fmaxf(s10, s11));
        }
    }
    mx0 = fmaxf(mx0, __shfl_xor_sync(0xffffffffu, mx0, 1));
    mx0 = fmaxf(mx0, __shfl_xor_sync(0xffffffffu, mx0, 2));
    mx1 = fmaxf(mx1, __shfl_xor_sync(0xffffffffu, mx1, 1));
    mx1 = fmaxf(mx1, __shfl_xor_sync(0xffffffffu, mx1, 2));
    if (th == 0) { redm[nw][r0] = mx0; redm[nw][r1] = mx1; }
    __syncthreads();

    float M0 = fmaxf(redm[0][r0], redm[1][r0]);
    float M1 = fmaxf(redm[0][r1], redm[1][r1]);

    float sm0 = 0.f, sm1 = 0.f;
    #pragma unroll
    for (int nt = 0; nt < 16; nt++) {
        if (nt < ntc) {
            float e00 = __expf(acc[nt][0] - M0);
            float e01 = __expf(acc[nt][1] - M0);
            float e10 = __expf(acc[nt][2] - M1);
            float e11 = __expf(acc[nt][3] - M1);
            acc[nt][0]=e00; acc[nt][1]=e01; acc[nt][2]=e10; acc[nt][3]=e11;
            sm0 += e00 + e01; sm1 += e10 + e11;
        }
    }
    sm0 += __shfl_xor_sync(0xffffffffu, sm0, 1);
    sm0 += __shfl_xor_sync(0xffffffffu, sm0, 2);
    sm1 += __shfl_xor_sync(0xffffffffu, sm1, 1);
    sm1 += __shfl_xor_sync(0xffffffffu, sm1, 2);
    if (th == 0) { reds[nw][r0] = sm0; reds[nw][r1] = sm1; }
    __syncthreads();

    float inv0 = 1.f / (reds[0][r0] + reds[1][r0]);
    float inv1 = 1.f / (reds[0][r1] + reds[1][r1]);

    __half* Pb = g_P + (size_t)b * NT * NT;
    #pragma unroll
    for (int nt = 0; nt < 16; nt++) {
        if (nt < ntc) {
            int c = base + nt*8 + 2*th;
            *(unsigned*)(Pb + (size_t)q0*NT + c) = h2(acc[nt][0]*inv0, acc[nt][1]*inv0);
            *(unsigned*)(Pb + (size_t)q1*NT + c) = h2(acc[nt][2]*inv1, acc[nt][3]*inv1);
        }
    }

    const int width = 256 - ncols;
    if (width > 0) {
        const int w8 = width >> 3;
        const uint4 zz = make_uint4(0,0,0,0);
        for (int i = tid; i < 64 * w8; i += 256) {
            int row = i / w8, cc = ncols + (i - row*w8)*8;
            *(uint4*)(Pb + (size_t)(qt0+row)*NT + cc) = zz;
        }
    }
}

// ============================================================================
// Kernel 3: O = P @ V (fp32 out). 3-stage cp.async, single barrier/k32-tile.
// Dynamic smem: Ps 3x(128x40), Vs 3x(32x136) halves.
// ============================================================================
#define PV_SMEM ((3*(128*40) + 3*(32*136))*2)   // 56832 B
__global__ __launch_bounds__(256) void pv_kernel(float* __restrict__ out)
{
    extern __shared__ __align__(16) __half dsm[];
    __half* Ps = dsm;            // stage stride 5120
    __half* Vs = dsm + 15360;    // stage stride 4352

    const int b  = blockIdx.z;
    const int m0 = blockIdx.x * 128, n0 = blockIdx.y * 128;
    const int tid  = threadIdx.x;
    const int lane = tid & 31, wid = tid >> 5;
    const int mw = wid & 3, nw = wid >> 2;
    const int g  = lane >> 2, th = lane & 3;
    const int nit = (m0 + 128) / 32;

    const __half* Pm = g_P + (size_t)b * NT * NT;
    const __half* Vm = g_V + (size_t)b * NT * NH;

    const int prow = tid >> 1, pco = (tid & 1) * 16;
    const int vrow = tid >> 3, vco = (tid & 7) * 16;
    const int aro = ((lane>>3)&1)*8 + (lane&7);
    const int akw = (lane>>4)*8;
    const int tro = (lane&7) + ((lane>>3)&1)*8;
    const int tno = (lane>>4)*8;

    float acc[2][8][4];
    #pragma unroll
    for (int i = 0; i < 2; i++)
        #pragma unroll
        for (int q = 0; q < 8; q++)
            #pragma unroll
            for (int p = 0; p < 4; p++) acc[i][q][p] = 0.f;

    auto issue = [&](int it, int st){
        if (it < nit) {
            const int k0 = it * 32;
            unsigned sP = su32(Ps + st*5120 + prow*40 + pco);
            const __half* gP = Pm + (size_t)(m0+prow)*NT + k0 + pco;
            CPA(sP,      gP);
            CPA(sP + 16, gP + 8);
            unsigned sV = su32(Vs + st*4352 + vrow*136 + vco);
            const __half* gV = Vm + (size_t)(k0+vrow)*NH + n0 + vco;
            CPA(sV,      gV);
            CPA(sV + 16, gV + 8);
        }
        CPC();
    };

    issue(0, 0);
    issue(1, 1);

    int rs = 0;
    for (int it = 0; it < nit; it++) {
        CPW(1);
        __syncthreads();
        int ws = rs + 2; if (ws >= 3) ws -= 3;
        issue(it + 2, ws);

        const __half* Psr = Ps + rs*5120;
        const __half* Vsr = Vs + rs*4352;
        #pragma unroll
        for (int ks = 0; ks < 2; ks++) {
            unsigned a0[4], a1[4];
            LDSM4(a0[0],a0[1],a0[2],a0[3], su32(Psr + (mw*32      + aro)*40 + akw + ks*16));
            LDSM4(a1[0],a1[1],a1[2],a1[3], su32(Psr + (mw*32 + 16 + aro)*40 + akw + ks*16));
            unsigned bb[8][2];
            #pragma unroll
            for (int c2 = 0; c2 < 4; c2++) {
                unsigned r0,r1,r2,r3;
                LDSM4T(r0,r1,r2,r3,
                    su32(Vsr + (ks*16 + tro)*136 + nw*64 + c2*16 + tno));
                bb[2*c2  ][0] = r0; bb[2*c2  ][1] = r1;
                bb[2*c2+1][0] = r2; bb[2*c2+1][1] = r3;
            }
            #pragma unroll
            for (int nt = 0; nt < 8; nt++) {
                mma16(acc[0][nt], a0, bb[nt]);
                mma16(acc[1][nt], a1, bb[nt]);
            }
        }
        rs = rs + 1; if (rs >= 3) rs -= 3;
    }

    #pragma unroll
    for (int mt = 0; mt < 2; mt++)
        #pragma unroll
        for (int nt = 0; nt < 8; nt++) {
            int row = m0 + mw*32 + mt*16 + g;
            int col = n0 + nw*64 + nt*8 + 2*th;
            size_t base_o = (size_t)(b*NT + row) * NH + col;
            *(float2*)(out + base_o)                = make_float2(acc[mt][nt][0], acc[mt][nt][1]);
            *(float2*)(out + base_o + (size_t)8*NH) = make_float2(acc[mt][nt][2], acc[mt][nt][3]);
        }
}

// ============================================================================
extern "C" void kernel_launch(void* const* d_in, const int* in_sizes, int n_in,
                              void* d_out, int out_size)
{
    const float* x  = (const float*)d_in[0];
    const float* Wk = (const float*)d_in[1];
    const float* Wq = (const float*)d_in[2];
    const float* Wv = (const float*)d_in[3];
    float* out = (float*)d_out;

    cudaFuncSetAttribute(proj_kernel, cudaFuncAttributeMaxDynamicSharedMemorySize, PROJ_SMEM);
    cudaFuncSetAttribute(pv_kernel,   cudaFuncAttributeMaxDynamicSharedMemorySize, PV_SMEM);

    cvt_kernel   <<<((NBT*NC/8) + 255) / 256, 256>>>(x, Wk, Wq, Wv);
    proj_kernel  <<<dim3(NBT/128, NH/128, 3), 256, PROJ_SMEM>>>();
    scores_kernel<<<dim3(NT/64,  NB),         256>>>();
    pv_kernel    <<<dim3(NT/128, NH/128, NB), 256, PV_SMEM>>>(out);
}

// round 9
// speedup vs baseline: 11.2385x; 1.0494x over previous
#include <cuda_runtime.h>
#include <cuda_fp16.h>
#include <cstdint>

#define NB 256
#define NT 256
#define NC 384
#define NH 384
#define NBT (NB*NT)

__device__ __half g_X16[(size_t)NBT*NC];
__device__ __half g_Wh[3][(size_t)NH*NC];
__device__ __half g_Q[(size_t)NBT*NH];
__device__ __half g_K[(size_t)NBT*NH];
__device__ __half g_V[(size_t)NBT*NH];

#define NEG_INF (__int_as_float((int)0xff800000))

__forceinline__ __device__ unsigned h2(float a, float b){
    __half2 h = __floats2half2_rn(a, b);
    return *reinterpret_cast<unsigned*>(&h);
}
__forceinline__ __device__ void mma16(float* c, const unsigned* a, const unsigned* b){
    asm("mma.sync.aligned.m16n8k16.row.col.f32.f16.f16.f32 "
        "{%0,%1,%2,%3}, {%4,%5,%6,%7}, {%8,%9}, {%0,%1,%2,%3};"
        : "+f"(c[0]), "+f"(c[1]), "+f"(c[2]), "+f"(c[3])
        : "r"(a[0]), "r"(a[1]), "r"(a[2]), "r"(a[3]), "r"(b[0]), "r"(b[1]));
}
__forceinline__ __device__ unsigned su32(const void* p){
    return (unsigned)__cvta_generic_to_shared(p);
}
#define CPA(dst,src) asm volatile("cp.async.ca.shared.global [%0], [%1], 16;" :: "r"(dst), "l"(src) : "memory")
#define CPC()        asm volatile("cp.async.commit_group;" ::: "memory")
#define CPW(n)       asm volatile("cp.async.wait_group %0;" :: "n"(n) : "memory")
#define LDSM4(r0,r1,r2,r3,a) \
    asm volatile("ldmatrix.sync.aligned.m8n8.x4.shared.b16 {%0,%1,%2,%3}, [%4];" \
        : "=r"(r0),"=r"(r1),"=r"(r2),"=r"(r3) : "r"(a))
#define LDSM4T(r0,r1,r2,r3,a) \
    asm volatile("ldmatrix.sync.aligned.m8n8.x4.trans.shared.b16 {%0,%1,%2,%3}, [%4];" \
        : "=r"(r0),"=r"(r1),"=r"(r2),"=r"(r3) : "r"(a))

// ============================================================================
// Kernel 0: fp32 -> fp16 preconvert of x and Wq/Wk/Wv.
// ============================================================================
__global__ __launch_bounds__(256) void cvt_kernel(
    const float* __restrict__ x, const float* __restrict__ Wk,
    const float* __restrict__ Wq, const float* __restrict__ Wv)
{
    const size_t t = (size_t)blockIdx.x * 256 + threadIdx.x;
    const size_t base = t * 8;
    if (base < (size_t)NBT*NC) {
        float4 f0 = *(const float4*)(x + base);
        float4 f1 = *(const float4*)(x + base + 4);
        *(uint4*)(g_X16 + base) = make_uint4(h2(f0.x,f0.y), h2(f0.z,f0.w),
                                             h2(f1.x,f1.y), h2(f1.z,f1.w));
    }
    if (t < (size_t)3*NH*NC/8) {
        const int w = (int)t * 8;
        const int sec = w / (NH*NC);
        const int off = w - sec * (NH*NC);
        const float* W = (sec == 0) ? Wq : (sec == 1 ? Wk : Wv);
        float4 f0 = *(const float4*)(W + off);
        float4 f1 = *(const float4*)(W + off + 4);
        *(uint4*)(g_Wh[sec] + off) = make_uint4(h2(f0.x,f0.y), h2(f0.z,f0.w),
                                                h2(f1.x,f1.y), h2(f1.z,f1.w));
    }
}

// ============================================================================
// Kernel 1 (unchanged from R8): QKV projection, 3-stage cp.async + ldmatrix.
// ============================================================================
#define PROJ_SMEM (3*(128*40)*2*2)   // 61440 B
__global__ __launch_bounds__(256) void proj_kernel()
{
    extern __shared__ __align__(16) __half dsm[];
    __half* As = dsm;            // stage stride 5120 halves
    __half* Bs = dsm + 15360;

    const int z = blockIdx.z;
    const __half* Xb = g_X16 + (size_t)(blockIdx.x*128)*NC;
    const __half* Wb = g_Wh[z] + (size_t)(blockIdx.y*128)*NC;
    __half* out = (z == 0 ? g_Q : (z == 1 ? g_K : g_V));

    const int m0 = blockIdx.x * 128, n0 = blockIdx.y * 128;
    const int tid  = threadIdx.x;
    const int lane = tid & 31, wid = tid >> 5;
    const int mw = wid & 3, nw = wid >> 2;
    const int g  = lane >> 2, th = lane & 3;

    const int frow = tid >> 1, fco = (tid & 1) * 16;
    const int arow = mw*32 + ((lane>>3)&1)*8 + (lane&7);
    const int akw  = (lane>>4)*8;
    const int brow = nw*64 + (lane>>4)*8 + (lane&7);
    const int bkw  = ((lane>>3)&1)*8;

    float acc[2][8][4];
    #pragma unroll
    for (int i = 0; i < 2; i++)
        #pragma unroll
        for (int q = 0; q < 8; q++)
            #pragma unroll
            for (int p = 0; p < 4; p++) acc[i][q][p] = 0.f;

    auto issue = [&](int it, int st){
        if (it < 12) {
            const int k0 = it * 32;
            const __half* gA = Xb + (size_t)frow*NC + k0 + fco;
            const __half* gB = Wb + (size_t)frow*NC + k0 + fco;
            unsigned sA = su32(As + st*5120 + frow*40 + fco);
            unsigned sB = su32(Bs + st*5120 + frow*40 + fco);
            CPA(sA,      gA);
            CPA(sA + 16, gA + 8);
            CPA(sB,      gB);
            CPA(sB + 16, gB + 8);
        }
        CPC();
    };

    issue(0, 0);
    issue(1, 1);

    int rs = 0;
    for (int it = 0; it < 12; it++) {
        CPW(1);
        __syncthreads();
        int ws = rs + 2; if (ws >= 3) ws -= 3;
        issue(it + 2, ws);

        const __half* Asr = As + rs*5120;
        const __half* Bsr = Bs + rs*5120;
        #pragma unroll
        for (int ks = 0; ks < 2; ks++) {
            unsigned a0[4], a1[4];
            LDSM4(a0[0],a0[1],a0[2],a0[3], su32(Asr +  arow     *40 + akw + ks*16));
            LDSM4(a1[0],a1[1],a1[2],a1[3], su32(Asr + (arow+16) *40 + akw + ks*16));
            unsigned b[8][2];
            #pragma unroll
            for (int p = 0; p < 4; p++) {
                unsigned r0,r1,r2,r3;
                LDSM4(r0,r1,r2,r3, su32(Bsr + (brow + p*16)*40 + bkw + ks*16));
                b[2*p  ][0] = r0; b[2*p  ][1] = r1;
                b[2*p+1][0] = r2; b[2*p+1][1] = r3;
            }
            #pragma unroll
            for (int nt = 0; nt < 8; nt++) {
                mma16(acc[0][nt], a0, b[nt]);
                mma16(acc[1][nt], a1, b[nt]);
            }
        }
        rs = rs + 1; if (rs >= 3) rs -= 3;
    }

    #pragma unroll
    for (int mt = 0; mt < 2; mt++)
        #pragma unroll
        for (int nt = 0; nt < 8; nt++) {
            int row = m0 + mw*32 + mt*16 + g;
            int col = n0 + nw*64 + nt*8 + 2*th;
            *(unsigned*)(out + (size_t)row*NH + col)     = h2(acc[mt][nt][0], acc[mt][nt][1]);
            *(unsigned*)(out + (size_t)(row+8)*NH + col) = h2(acc[mt][nt][2], acc[mt][nt][3]);
        }
}

// ============================================================================
// Kernel 2: FUSED attention: S = scale*QK^T (causal) -> softmax -> P (smem)
// -> O = P@V -> gmem fp32. One CTA per (64-query tile, batch).
// Phase 1: k-tile 32, 3-stage cp.async; K rows loaded only up to ncols.
// Phase 2: P in smem (stride 264), V double-buffered 64-col chunks (stride 72).
// ============================================================================
#define FA_SMEM 107520   // max(phase1 76800, phase2 107520) bytes
__global__ __launch_bounds__(256) void attn_kernel(float* __restrict__ out)
{
    extern __shared__ __align__(16) __half dsm[];
    __shared__ float redm[2][64];
    __shared__ float reds[2][64];

    const int b = blockIdx.y, bx = blockIdx.x;
    const int qt0 = bx * 64, ncols = qt0 + 64;
    const int jmax = ncols >> 4;             // 16-k tiles in phase 2
    const int tid  = threadIdx.x;
    const int lane = tid & 31, wid = tid >> 5;
    const int mw = wid & 3, nw = wid >> 2;
    const int g  = lane >> 2, th = lane & 3;
    const int base = nw * 128;
    int ntc = (ncols - base) / 8;
    ntc = ntc < 0 ? 0 : (ntc > 16 ? 16 : ntc);
    const int npt = ntc >> 1;                // 16-col tile pairs

    const __half* Qm = g_Q + (size_t)b * NT * NH;
    const __half* Km = g_K + (size_t)b * NT * NH;
    const __half* Vm = g_V + (size_t)b * NT * NH;

    const int aro = ((lane>>3)&1)*8 + (lane&7);
    const int akw = (lane>>4)*8;
    const int bro = (lane>>4)*8 + (lane&7);
    const int bkw = ((lane>>3)&1)*8;
    const int tro = (lane&7) + ((lane>>3)&1)*8;
    const int tno = (lane>>4)*8;

    __half* Qs = dsm;            // 3 stages x 64*40
    __half* Ks = dsm + 7680;     // 3 stages x 256*40

    float acc[16][4];
    #pragma unroll
    for (int i = 0; i < 16; i++)
        #pragma unroll
        for (int p = 0; p < 4; p++) acc[i][p] = 0.f;

    const int frow = tid >> 2, fcol = (tid & 3) * 8;   // 16B per thread per row
    const int kpasses = ncols >> 6;                    // K rows / 64

    auto issue = [&](int it, int st){
        if (it < 12) {
            const int k0 = it * 32;
            CPA(su32(Qs + st*2560 + frow*40 + fcol),
                Qm + (size_t)(qt0+frow)*NH + k0 + fcol);
            for (int p = 0; p < kpasses; p++) {
                int r = p*64 + frow;
                CPA(su32(Ks + st*10240 + r*40 + fcol),
                    Km + (size_t)r*NH + k0 + fcol);
            }
        }
        CPC();
    };

    issue(0, 0);
    issue(1, 1);

    int rs = 0;
    for (int it = 0; it < 12; it++) {
        CPW(1);
        __syncthreads();
        int ws = rs + 2; if (ws >= 3) ws -= 3;
        issue(it + 2, ws);

        if (npt > 0) {
            const __half* Qr = Qs + rs*2560;
            const __half* Kr = Ks + rs*10240;
            #pragma unroll
            for (int ks = 0; ks < 2; ks++) {
                unsigned a[4];
                LDSM4(a[0],a[1],a[2],a[3], su32(Qr + (mw*16 + aro)*40 + akw + ks*16));
                #pragma unroll
                for (int p = 0; p < 8; p++) {
                    if (p < npt) {
                        unsigned r0,r1,r2,r3;
                        LDSM4(r0,r1,r2,r3, su32(Kr + (base + p*16 + bro)*40 + bkw + ks*16));
                        unsigned b0[2] = {r0,r1}, b1[2] = {r2,r3};
                        mma16(acc[2*p],   a, b0);
                        mma16(acc[2*p+1], a, b1);
                    }
                }
            }
        }
        rs = rs + 1; if (rs >= 3) rs -= 3;
    }

    // ---------------- softmax (fragment-resident) ----------------
    const float scale = 0.05103103630798288f;  // 384^-0.5
    const int r0 = mw*16 + g, r1 = r0 + 8;
    const int q0 = qt0 + r0, q1 = qt0 + r1;

    float mx0 = NEG_INF, mx1 = NEG_INF;
    #pragma unroll
    for (int nt = 0; nt < 16; nt++) {
        if (nt < ntc) {
            int c = base + nt*8 + 2*th;
            float s00 = (c   <= q0) ? acc[nt][0]*scale : NEG_INF;
            float s01 = (c+1 <= q0) ? acc[nt][1]*scale : NEG_INF;
            float s10 = (c   <= q1) ? acc[nt][2]*scale : NEG_INF;
            float s11 = (c+1 <= q1) ? acc[nt][3]*scale : NEG_INF;
            acc[nt][0]=s00; acc[nt][1]=s01; acc[nt][2]=s10; acc[nt][3]=s11;
            mx0 = fmaxf(mx0, fmaxf(s00, s01));
            mx1 = fmaxf(mx1, fmaxf(s10, s11));
        }
    }
    mx0 = fmaxf(mx0, __shfl_xor_sync(0xffffffffu, mx0, 1));
    mx0 = fmaxf(mx0, __shfl_xor_sync(0xffffffffu, mx0, 2));
    mx1 = fmaxf(mx1, __shfl_xor_sync(0xffffffffu, mx1, 1));
    mx1 = fmaxf(mx1, __shfl_xor_sync(0xffffffffu, mx1, 2));
    if (th == 0) { redm[nw][r0] = mx0; redm[nw][r1] = mx1; }
    __syncthreads();

    float M0 = fmaxf(redm[0][r0], redm[1][r0]);
    float M1 = fmaxf(redm[0][r1], redm[1][r1]);

    float sm0 = 0.f, sm1 = 0.f;
    #pragma unroll
    for (int nt = 0; nt < 16; nt++) {
        if (nt < ntc) {
            float e00 = __expf(acc[nt][0] - M0);
            float e01 = __expf(acc[nt][1] - M0);
            float e10 = __expf(acc[nt][2] - M1);
            float e11 = __expf(acc[nt][3] - M1);
            acc[nt][0]=e00; acc[nt][1]=e01; acc[nt][2]=e10; acc[nt][3]=e11;
            sm0 += e00 + e01; sm1 += e10 + e11;
        }
    }
    sm0 += __shfl_xor_sync(0xffffffffu, sm0, 1);
    sm0 += __shfl_xor_sync(0xffffffffu, sm0, 2);
    sm1 += __shfl_xor_sync(0xffffffffu, sm1, 1);
    sm1 += __shfl_xor_sync(0xffffffffu, sm1, 2);
    if (th == 0) { reds[nw][r0] = sm0; reds[nw][r1] = sm1; }
    __syncthreads();

    float inv0 = 1.f / (reds[0][r0] + reds[1][r0]);
    float inv1 = 1.f / (reds[0][r1] + reds[1][r1]);

    // ---------------- P -> smem (overlays phase-1 buffers) ----------------
    __half* Ps = dsm;                         // 64 x 264
    #pragma unroll
    for (int nt = 0; nt < 16; nt++) {
        if (nt < ntc) {
            int c = base + nt*8 + 2*th;
            *(unsigned*)&Ps[r0*264 + c] = h2(acc[nt][0]*inv0, acc[nt][1]*inv0);
            *(unsigned*)&Ps[r1*264 + c] = h2(acc[nt][2]*inv1, acc[nt][3]*inv1);
        }
    }
    __syncthreads();

    // ---------------- phase 2: O = P @ V ----------------
    __half* Vb = dsm + 16896;                 // 2 stages x 256*72
    const int vrow = tid >> 3, vcol = (tid & 7) * 8;
    const int vpasses = ncols >> 5;           // V rows / 32

    auto issueV = [&](int c, int st){
        if (c < 6) {
            for (int p = 0; p < vpasses; p++) {
                int r = p*32 + vrow;
                CPA(su32(Vb + st*18432 + r*72 + vcol),
                    Vm + (size_t)r*NH + c*64 + vcol);
            }
        }
        CPC();
    };

    issueV(0, 0);
    issueV(1, 1);

    for (int c = 0; c < 6; c++) {
        CPW(1);
        __syncthreads();
        const __half* Vr = Vb + (c & 1)*18432;

        float o[4][4];
        #pragma unroll
        for (int nt = 0; nt < 4; nt++)
            #pragma unroll
            for (int p = 0; p < 4; p++) o[nt][p] = 0.f;

        for (int jt = 0; jt < jmax; jt++) {
            unsigned a[4];
            LDSM4(a[0],a[1],a[2],a[3], su32(Ps + (mw*16 + aro)*264 + jt*16 + akw));
            unsigned bb[4][2];
            #pragma unroll
            for (int cg = 0; cg < 2; cg++) {
                unsigned v0,v1,v2,v3;
                LDSM4T(v0,v1,v2,v3,
                    su32(Vr + (jt*16 + tro)*72 + nw*32 + cg*16 + tno));
                bb[2*cg  ][0] = v0; bb[2*cg  ][1] = v1;
                bb[2*cg+1][0] = v2; bb[2*cg+1][1] = v3;
            }
            #pragma unroll
            for (int nt = 0; nt < 4; nt++) mma16(o[nt], a, bb[nt]);
        }

        #pragma unroll
        for (int nt = 0; nt < 4; nt++) {
            int row = qt0 + mw*16 + g;
            int col = c*64 + nw*32 + nt*8 + 2*th;
            size_t bo = (size_t)(b*NT + row) * NH + col;
            *(float2*)(out + bo)                = make_float2(o[nt][0], o[nt][1]);
            *(float2*)(out + bo + (size_t)8*NH) = make_float2(o[nt][2], o[nt][3]);
        }
        __syncthreads();
        issueV(c + 2, c & 1);
    }
}

// ============================================================================
extern "C" void kernel_launch(void* const* d_in, const int* in_sizes, int n_in,
                              void* d_out, int out_size)
{
    const float* x  = (const float*)d_in[0];
    const float* Wk = (const float*)d_in[1];
    const float* Wq = (const float*)d_in[2];
    const float* Wv = (const float*)d_in[3];
    float* out = (float*)d_out;

    cudaFuncSetAttribute(proj_kernel, cudaFuncAttributeMaxDynamicSharedMemorySize, PROJ_SMEM);
    cudaFuncSetAttribute(attn_kernel, cudaFuncAttributeMaxDynamicSharedMemorySize, FA_SMEM);

    cvt_kernel <<<((NBT*NC/8) + 255) / 256, 256>>>(x, Wk, Wq, Wv);
    proj_kernel<<<dim3(NBT/128, NH/128, 3), 256, PROJ_SMEM>>>();
    attn_kernel<<<dim3(NT/64, NB), 256, FA_SMEM>>>(out);
}